// round 4
// baseline (speedup 1.0000x reference)
#include <cuda_runtime.h>

// ---------------------------------------------------------------------------
// GraphSAGE forward, fp32.
//   h = x @ Win + b_in                                  [100000, 64]
//   4x: agg = scatter_mean(h[src] -> dst)
//       h  += relu( agg @ Wl[i] + bl[i] + h @ Wr[i] )
//   out = h @ Wout + b_out                              [100000, 256]
// ---------------------------------------------------------------------------

#define NMAX 100000
#define EMAX 3200000
#define HD   64

// Scratch (static device globals — no runtime allocation). 16B-aligned for
// float4 / red.v4 access.
__device__ __align__(16) float d_h[(size_t)NMAX * HD];
__device__ __align__(16) float d_agg[(size_t)NMAX * HD];
__device__ __align__(16) int   d_src[EMAX];
__device__ __align__(16) int   d_dst[EMAX];
__device__ __align__(16) int   d_cnt[NMAX];
__device__ __align__(16) float d_inv[NMAX];
__device__ int d_is64;   // 1 if edge_index arrived as int64, 0 if int32

// ---------------------------------------------------------------------------
__global__ void k_zero4(float* __restrict__ p, int n4) {
    int i = blockIdx.x * blockDim.x + threadIdx.x;
    if (i < n4) ((float4*)p)[i] = make_float4(0.f, 0.f, 0.f, 0.f);
}

// Detect whether the edge buffer is int64 (as in the reference) or was
// lowered to int32 by the harness. For int64 values < 2^31 every high word
// is zero; for 3.2M random int32 indices the odd slots are nonzero with
// probability ~1. Deterministic, single block.
__global__ void k_detect(const int* __restrict__ ei32) {
    __shared__ int nz;
    if (threadIdx.x == 0) nz = 0;
    __syncthreads();
    int local = 0;
    for (int i = threadIdx.x; i < 2048; i += blockDim.x)
        if (ei32[2 * i + 1] != 0) local = 1;
    if (local) atomicOr(&nz, 1);
    __syncthreads();
    if (threadIdx.x == 0) d_is64 = (nz == 0) ? 1 : 0;
}

// Decode edge index -> int32 src/dst (clamped), count in-degrees.
__global__ void k_edges(const int* __restrict__ ei32, int E) {
    int e = blockIdx.x * blockDim.x + threadIdx.x;
    if (e >= E) return;
    int s, d;
    if (d_is64) {                       // little-endian int64: low word
        s = ei32[2 * (size_t)e];
        d = ei32[2 * ((size_t)E + e)];
    } else {                            // plain int32
        s = ei32[e];
        d = ei32[(size_t)E + e];
    }
    s = min(max(s, 0), NMAX - 1);
    d = min(max(d, 0), NMAX - 1);
    d_src[e] = s;
    d_dst[e] = d;
    atomicAdd(&d_cnt[d], 1);
}

__global__ void k_inv(int N) {
    int n = blockIdx.x * blockDim.x + threadIdx.x;
    if (n < N) d_inv[n] = 1.0f / (float)max(d_cnt[n], 1);
}

// Scatter-add: 16 threads per edge, one float4 each.
// h row = 256B, read via LDG.128 (coalesced), accumulate via red.global.add.v4.
__global__ void k_scatter(int E) {
    int t = blockIdx.x * blockDim.x + threadIdx.x;
    int e = t >> 4;
    int j = t & 15;
    if (e >= E) return;
    int s = d_src[e];
    int d = d_dst[e];
    float4 v = *(((const float4*)d_h) + (size_t)s * 16 + j);
    float* p = d_agg + ((size_t)d * HD + j * 4);
    asm volatile("red.global.add.v4.f32 [%0], {%1,%2,%3,%4};"
                 :: "l"(p), "f"(v.x), "f"(v.y), "f"(v.z), "f"(v.w)
                 : "memory");
}

// ---------------------------------------------------------------------------
// Tiled fp32 GEMM cores: BM=64, BN=64, 256 threads, 4x4 microtile.
// As stored transposed As[k][m] (row stride 68 keeps 16B alignment) so the
// microkernel is 2x LDS.128 + 16 FFMA per k.
// ---------------------------------------------------------------------------

#define FMA16(acc, a, b)                                        \
    { float av_[4] = {a.x, a.y, a.z, a.w};                      \
      float bv_[4] = {b.x, b.y, b.z, b.w};                      \
      _Pragma("unroll") for (int i_ = 0; i_ < 4; i_++)          \
      _Pragma("unroll") for (int j_ = 0; j_ < 4; j_++)          \
          acc[i_][j_] += av_[i_] * bv_[j_]; }

// h = x @ Win + b_in   (M x 512 @ 512 x 64)
__global__ void __launch_bounds__(256) k_gemm_in(
    const float* __restrict__ x, const float* __restrict__ Win,
    const float* __restrict__ b_in, int M)
{
    __shared__ float As[32][68];
    __shared__ float Bs[32][64];
    int tid = threadIdx.x;
    int r0  = blockIdx.x * 64;
    int tr  = tid >> 4, tc = tid & 15;
    float acc[4][4] = {};

    for (int k0 = 0; k0 < 512; k0 += 32) {
        #pragma unroll
        for (int r = 0; r < 2; r++) {
            int i  = tid + 256 * r;      // float4 index 0..511
            int m  = i >> 3;             // 8 float4 per row (32 k)
            int kq = i & 7;
            int row = r0 + m;
            float4 a = make_float4(0.f, 0.f, 0.f, 0.f);
            if (row < M) a = *(const float4*)(x + (size_t)row * 512 + k0 + kq * 4);
            As[kq * 4 + 0][m] = a.x; As[kq * 4 + 1][m] = a.y;
            As[kq * 4 + 2][m] = a.z; As[kq * 4 + 3][m] = a.w;
        }
        #pragma unroll
        for (int r = 0; r < 2; r++) {
            int i  = tid + 256 * r;
            int kk = i >> 4;
            int n4 = i & 15;
            *(float4*)&Bs[kk][n4 * 4] =
                *(const float4*)(Win + (size_t)(k0 + kk) * 64 + n4 * 4);
        }
        __syncthreads();
        #pragma unroll
        for (int kk = 0; kk < 32; kk++) {
            float4 a = *(float4*)&As[kk][tr * 4];
            float4 b = *(float4*)&Bs[kk][tc * 4];
            FMA16(acc, a, b);
        }
        __syncthreads();
    }

    float4 bb = *(const float4*)(b_in + tc * 4);
    #pragma unroll
    for (int i = 0; i < 4; i++) {
        int row = r0 + tr * 4 + i;
        if (row < M) {
            float4 o;
            o.x = acc[i][0] + bb.x; o.y = acc[i][1] + bb.y;
            o.z = acc[i][2] + bb.z; o.w = acc[i][3] + bb.w;
            *(float4*)(d_h + (size_t)row * HD + tc * 4) = o;
        }
    }
}

// h += relu( (agg .* inv) @ Wl + bl + h @ Wr )   — concat K=128 GEMM, in place.
__global__ void __launch_bounds__(256) k_layer(
    const float* __restrict__ Wl, const float* __restrict__ bl,
    const float* __restrict__ Wr, int M)
{
    __shared__ float As[32][68];
    __shared__ float Bs[32][64];
    int tid = threadIdx.x;
    int r0  = blockIdx.x * 64;
    int tr  = tid >> 4, tc = tid & 15;
    float acc[4][4] = {};

    #pragma unroll
    for (int phase = 0; phase < 2; phase++) {
        const float* A = phase ? d_h : d_agg;
        const float* B = phase ? Wr : Wl;
        #pragma unroll
        for (int k0 = 0; k0 < 64; k0 += 32) {
            #pragma unroll
            for (int r = 0; r < 2; r++) {
                int i  = tid + 256 * r;
                int m  = i >> 3;
                int kq = i & 7;
                int row = r0 + m;
                float4 a = make_float4(0.f, 0.f, 0.f, 0.f);
                if (row < M) {
                    a = *(const float4*)(A + (size_t)row * HD + k0 + kq * 4);
                    if (phase == 0) {
                        float s = d_inv[row];
                        a.x *= s; a.y *= s; a.z *= s; a.w *= s;
                    }
                }
                As[kq * 4 + 0][m] = a.x; As[kq * 4 + 1][m] = a.y;
                As[kq * 4 + 2][m] = a.z; As[kq * 4 + 3][m] = a.w;
            }
            #pragma unroll
            for (int r = 0; r < 2; r++) {
                int i  = tid + 256 * r;
                int kk = i >> 4;
                int n4 = i & 15;
                *(float4*)&Bs[kk][n4 * 4] =
                    *(const float4*)(B + (size_t)(k0 + kk) * 64 + n4 * 4);
            }
            __syncthreads();
            #pragma unroll
            for (int kk = 0; kk < 32; kk++) {
                float4 a = *(float4*)&As[kk][tr * 4];
                float4 b = *(float4*)&Bs[kk][tc * 4];
                FMA16(acc, a, b);
            }
            __syncthreads();
        }
    }

    float4 bb = *(const float4*)(bl + tc * 4);
    #pragma unroll
    for (int i = 0; i < 4; i++) {
        int row = r0 + tr * 4 + i;
        if (row < M) {
            float4 h4 = *(float4*)(d_h + (size_t)row * HD + tc * 4);
            float4 o;
            o.x = h4.x + fmaxf(acc[i][0] + bb.x, 0.f);
            o.y = h4.y + fmaxf(acc[i][1] + bb.y, 0.f);
            o.z = h4.z + fmaxf(acc[i][2] + bb.z, 0.f);
            o.w = h4.w + fmaxf(acc[i][3] + bb.w, 0.f);
            *(float4*)(d_h + (size_t)row * HD + tc * 4) = o;
        }
    }
}

// out = h @ Wout + b_out   (M x 64 @ 64 x 256), grid.y tiles N.
__global__ void __launch_bounds__(256) k_gemm_out(
    const float* __restrict__ Wout, const float* __restrict__ b_out,
    float* __restrict__ out, int M)
{
    __shared__ float As[32][68];
    __shared__ float Bs[32][64];
    int tid = threadIdx.x;
    int r0  = blockIdx.x * 64;
    int n0  = blockIdx.y * 64;
    int tr  = tid >> 4, tc = tid & 15;
    float acc[4][4] = {};

    #pragma unroll
    for (int k0 = 0; k0 < 64; k0 += 32) {
        #pragma unroll
        for (int r = 0; r < 2; r++) {
            int i  = tid + 256 * r;
            int m  = i >> 3;
            int kq = i & 7;
            int row = r0 + m;
            float4 a = make_float4(0.f, 0.f, 0.f, 0.f);
            if (row < M) a = *(const float4*)(d_h + (size_t)row * HD + k0 + kq * 4);
            As[kq * 4 + 0][m] = a.x; As[kq * 4 + 1][m] = a.y;
            As[kq * 4 + 2][m] = a.z; As[kq * 4 + 3][m] = a.w;
        }
        #pragma unroll
        for (int r = 0; r < 2; r++) {
            int i  = tid + 256 * r;
            int kk = i >> 4;
            int n4 = i & 15;
            *(float4*)&Bs[kk][n4 * 4] =
                *(const float4*)(Wout + (size_t)(k0 + kk) * 256 + n0 + n4 * 4);
        }
        __syncthreads();
        #pragma unroll
        for (int kk = 0; kk < 32; kk++) {
            float4 a = *(float4*)&As[kk][tr * 4];
            float4 b = *(float4*)&Bs[kk][tc * 4];
            FMA16(acc, a, b);
        }
        __syncthreads();
    }

    float4 bb = *(const float4*)(b_out + n0 + tc * 4);
    #pragma unroll
    for (int i = 0; i < 4; i++) {
        int row = r0 + tr * 4 + i;
        if (row < M) {
            float4 o;
            o.x = acc[i][0] + bb.x; o.y = acc[i][1] + bb.y;
            o.z = acc[i][2] + bb.z; o.w = acc[i][3] + bb.w;
            *(float4*)(out + (size_t)row * 256 + n0 + tc * 4) = o;
        }
    }
}

// ---------------------------------------------------------------------------
extern "C" void kernel_launch(void* const* d_in, const int* in_sizes, int n_in,
                              void* d_out, int out_size)
{
    const float* x     = (const float*)d_in[0];
    const int*   ei32  = (const int*)d_in[1];   // int32 view of edge_index
    const float* Win   = (const float*)d_in[2];
    const float* b_in  = (const float*)d_in[3];
    const float* Wl    = (const float*)d_in[4];
    const float* bl    = (const float*)d_in[5];
    const float* Wr    = (const float*)d_in[6];
    const float* Wout  = (const float*)d_in[7];
    const float* b_out = (const float*)d_in[8];
    float*       out   = (float*)d_out;

    int N = in_sizes[0] / 512;   // 100000
    int E = in_sizes[1] / 2;     // 3200000 (element count is 2E either way)

    float* cntp = nullptr;
    float* aggp = nullptr;
    cudaGetSymbolAddress((void**)&cntp, d_cnt);
    cudaGetSymbolAddress((void**)&aggp, d_agg);

    // Edge decode (dtype-robust) + degree count.
    k_detect<<<1, 256>>>(ei32);
    k_zero4<<<(N / 4 + 255) / 256, 256>>>(cntp, N / 4);
    k_edges<<<(E + 255) / 256, 256>>>(ei32, E);
    k_inv<<<(N + 255) / 256, 256>>>(N);

    // Input projection.
    k_gemm_in<<<(N + 63) / 64, 256>>>(x, Win, b_in, N);

    // 4 SAGE layers.
    int agg4 = N * (HD / 4);
    for (int l = 0; l < 4; l++) {
        k_zero4<<<(agg4 + 255) / 256, 256>>>(aggp, agg4);
        k_scatter<<<(E * 16 + 255) / 256, 256>>>(E);
        k_layer<<<(N + 63) / 64, 256>>>(Wl + (size_t)l * HD * HD,
                                        bl + (size_t)l * HD,
                                        Wr + (size_t)l * HD * HD, N);
    }

    // Output projection.
    dim3 g((N + 63) / 64, 4);
    k_gemm_out<<<g, 256>>>(Wout, b_out, out, N);
}

// round 5
// speedup vs baseline: 1.4995x; 1.4995x over previous
#include <cuda_runtime.h>
#include <cuda_fp16.h>

// ---------------------------------------------------------------------------
// GraphSAGE forward, fp32 master / fp16 message gather.
//   h = x @ Win + b_in                                  [100000, 64]
//   4x: agg = scatter_mean(h[src] -> dst)   (CSR gather-reduce, fp16 reads)
//       h  += relu( agg @ Wl[i] + bl[i] + h @ Wr[i] )
//   out = h @ Wout + b_out                              [100000, 256]
// ---------------------------------------------------------------------------

#define NMAX 100000
#define EMAX 3200000
#define HD   64

__device__ __align__(16) float  d_h[(size_t)NMAX * HD];
__device__ __align__(16) __half d_hh[(size_t)NMAX * HD];   // fp16 shadow of h
__device__ __align__(16) float  d_agg[(size_t)NMAX * HD];
__device__ __align__(16) int    d_src[EMAX];
__device__ __align__(16) int    d_dst[EMAX];
__device__ __align__(16) int    d_csr[EMAX];               // src sorted by dst
__device__ __align__(16) int    d_cnt[NMAX];
__device__ __align__(16) int    d_row[NMAX + 1];           // CSR row starts
__device__ __align__(16) int    d_woff[NMAX];              // fill cursors
__device__ __align__(16) float  d_inv[NMAX];
__device__ int d_bsum[512];
__device__ int d_boff[512];
__device__ int d_is64;

// ---------------------------------------------------------------------------
// Prep: zero degree counts; block 0 also detects edge dtype (int64 vs int32).
__global__ void k_prep(const int* __restrict__ ei32, int N) {
    __shared__ int nz;
    int i = blockIdx.x * blockDim.x + threadIdx.x;
    if (i < N) d_cnt[i] = 0;
    if (blockIdx.x == 0) {
        if (threadIdx.x == 0) nz = 0;
        __syncthreads();
        int local = 0;
        for (int j = threadIdx.x; j < 2048; j += blockDim.x)
            if (ei32[2 * j + 1] != 0) local = 1;
        if (local) atomicOr(&nz, 1);
        __syncthreads();
        if (threadIdx.x == 0) d_is64 = (nz == 0) ? 1 : 0;
    }
}

// Decode edge index -> int32 src/dst (clamped), count in-degrees.
__global__ void k_edges(const int* __restrict__ ei32, int E) {
    int e = blockIdx.x * blockDim.x + threadIdx.x;
    if (e >= E) return;
    int s, d;
    if (d_is64) {
        s = ei32[2 * (size_t)e];
        d = ei32[2 * ((size_t)E + e)];
    } else {
        s = ei32[e];
        d = ei32[(size_t)E + e];
    }
    s = min(max(s, 0), NMAX - 1);
    d = min(max(d, 0), NMAX - 1);
    d_src[e] = s;
    d_dst[e] = d;
    atomicAdd(&d_cnt[d], 1);
}

// Per-block sums of counts (scan level 1).
__global__ void k_bsum(int N) {
    __shared__ int sh[256];
    int i = blockIdx.x * 256 + threadIdx.x;
    int v = (i < N) ? d_cnt[i] : 0;
    sh[threadIdx.x] = v;
    __syncthreads();
    for (int s = 128; s > 0; s >>= 1) {
        if (threadIdx.x < s) sh[threadIdx.x] += sh[threadIdx.x + s];
        __syncthreads();
    }
    if (threadIdx.x == 0) d_bsum[blockIdx.x] = sh[0];
}

// Exclusive scan of block sums (single block, nb <= 512).
__global__ void k_bscan(int nb) {
    __shared__ int sh[512];
    int v = (threadIdx.x < nb) ? d_bsum[threadIdx.x] : 0;
    sh[threadIdx.x] = v;
    __syncthreads();
    for (int off = 1; off < 512; off <<= 1) {
        int t = (threadIdx.x >= off) ? sh[threadIdx.x - off] : 0;
        __syncthreads();
        sh[threadIdx.x] += t;
        __syncthreads();
    }
    if (threadIdx.x < nb) d_boff[threadIdx.x] = sh[threadIdx.x] - v;
}

// Final row starts + fill cursors + inverse degree.
__global__ void k_rows(int N, int E) {
    __shared__ int sh[256];
    int i = blockIdx.x * 256 + threadIdx.x;
    int v = (i < N) ? d_cnt[i] : 0;
    sh[threadIdx.x] = v;
    __syncthreads();
    for (int off = 1; off < 256; off <<= 1) {
        int t = (threadIdx.x >= off) ? sh[threadIdx.x - off] : 0;
        __syncthreads();
        sh[threadIdx.x] += t;
        __syncthreads();
    }
    int excl = sh[threadIdx.x] - v + d_boff[blockIdx.x];
    if (i < N) {
        d_row[i]  = excl;
        d_woff[i] = excl;
        d_inv[i]  = 1.0f / (float)max(v, 1);
    }
    if (i == N - 1) d_row[N] = E;
}

// Bucket-fill CSR (int atomics on 100k spread cursors — cheap).
__global__ void k_fill(int E) {
    int e = blockIdx.x * blockDim.x + threadIdx.x;
    if (e >= E) return;
    int pos = atomicAdd(&d_woff[d_dst[e]], 1);
    d_csr[pos] = d_src[e];
}

// ---------------------------------------------------------------------------
// Aggregation: one warp per node, fp16 gather, fp32 accumulate, scale by inv.
// Each lane owns 2 features (one __half2 = 4B; warp reads a full 128B row).
__global__ void __launch_bounds__(256) k_aggr(int N) {
    int w    = (blockIdx.x * blockDim.x + threadIdx.x) >> 5;
    int lane = threadIdx.x & 31;
    if (w >= N) return;
    int beg = d_row[w], end = d_row[w + 1];
    const __half2* hh = (const __half2*)d_hh;   // 32 half2 per row
    float2 acc = make_float2(0.f, 0.f);
    int i = beg;
    for (; i + 4 <= end; i += 4) {
        int s0 = d_csr[i], s1 = d_csr[i + 1], s2 = d_csr[i + 2], s3 = d_csr[i + 3];
        __half2 v0 = hh[(size_t)s0 * 32 + lane];
        __half2 v1 = hh[(size_t)s1 * 32 + lane];
        __half2 v2 = hh[(size_t)s2 * 32 + lane];
        __half2 v3 = hh[(size_t)s3 * 32 + lane];
        float2 f0 = __half22float2(v0), f1 = __half22float2(v1);
        float2 f2 = __half22float2(v2), f3 = __half22float2(v3);
        acc.x += (f0.x + f1.x) + (f2.x + f3.x);
        acc.y += (f0.y + f1.y) + (f2.y + f3.y);
    }
    for (; i < end; i++) {
        float2 f = __half22float2(hh[(size_t)d_csr[i] * 32 + lane]);
        acc.x += f.x;
        acc.y += f.y;
    }
    float inv = d_inv[w];
    ((float2*)d_agg)[(size_t)w * 32 + lane] = make_float2(acc.x * inv, acc.y * inv);
}

// ---------------------------------------------------------------------------
// Tiled fp32 GEMM cores: BM=64, BN=64, 256 threads, 4x4 microtile.
// ---------------------------------------------------------------------------

#define FMA16(acc, a, b)                                        \
    { float av_[4] = {a.x, a.y, a.z, a.w};                      \
      float bv_[4] = {b.x, b.y, b.z, b.w};                      \
      _Pragma("unroll") for (int i_ = 0; i_ < 4; i_++)          \
      _Pragma("unroll") for (int j_ = 0; j_ < 4; j_++)          \
          acc[i_][j_] += av_[i_] * bv_[j_]; }

__device__ __forceinline__ void store_hh(int row, int c4, float4 o) {
    __half2 p0 = __floats2half2_rn(o.x, o.y);
    __half2 p1 = __floats2half2_rn(o.z, o.w);
    uint2 u = make_uint2(*(unsigned*)&p0, *(unsigned*)&p1);
    *(uint2*)(d_hh + (size_t)row * HD + c4 * 4) = u;
}

// h = x @ Win + b_in   (M x 512 @ 512 x 64)
__global__ void __launch_bounds__(256) k_gemm_in(
    const float* __restrict__ x, const float* __restrict__ Win,
    const float* __restrict__ b_in, int M)
{
    __shared__ float As[32][68];
    __shared__ float Bs[32][64];
    int tid = threadIdx.x;
    int r0  = blockIdx.x * 64;
    int tr  = tid >> 4, tc = tid & 15;
    float acc[4][4] = {};

    for (int k0 = 0; k0 < 512; k0 += 32) {
        #pragma unroll
        for (int r = 0; r < 2; r++) {
            int i  = tid + 256 * r;
            int m  = i >> 3;
            int kq = i & 7;
            int row = r0 + m;
            float4 a = make_float4(0.f, 0.f, 0.f, 0.f);
            if (row < M) a = *(const float4*)(x + (size_t)row * 512 + k0 + kq * 4);
            As[kq * 4 + 0][m] = a.x; As[kq * 4 + 1][m] = a.y;
            As[kq * 4 + 2][m] = a.z; As[kq * 4 + 3][m] = a.w;
        }
        #pragma unroll
        for (int r = 0; r < 2; r++) {
            int i  = tid + 256 * r;
            int kk = i >> 4;
            int n4 = i & 15;
            *(float4*)&Bs[kk][n4 * 4] =
                *(const float4*)(Win + (size_t)(k0 + kk) * 64 + n4 * 4);
        }
        __syncthreads();
        #pragma unroll
        for (int kk = 0; kk < 32; kk++) {
            float4 a = *(float4*)&As[kk][tr * 4];
            float4 b = *(float4*)&Bs[kk][tc * 4];
            FMA16(acc, a, b);
        }
        __syncthreads();
    }

    float4 bb = *(const float4*)(b_in + tc * 4);
    #pragma unroll
    for (int i = 0; i < 4; i++) {
        int row = r0 + tr * 4 + i;
        if (row < M) {
            float4 o;
            o.x = acc[i][0] + bb.x; o.y = acc[i][1] + bb.y;
            o.z = acc[i][2] + bb.z; o.w = acc[i][3] + bb.w;
            *(float4*)(d_h + (size_t)row * HD + tc * 4) = o;
            store_hh(row, tc, o);
        }
    }
}

// h += relu( agg @ Wl + bl + h @ Wr )  — concat K=128 GEMM, in place.
__global__ void __launch_bounds__(256) k_layer(
    const float* __restrict__ Wl, const float* __restrict__ bl,
    const float* __restrict__ Wr, int M)
{
    __shared__ float As[32][68];
    __shared__ float Bs[32][64];
    int tid = threadIdx.x;
    int r0  = blockIdx.x * 64;
    int tr  = tid >> 4, tc = tid & 15;
    float acc[4][4] = {};

    #pragma unroll
    for (int phase = 0; phase < 2; phase++) {
        const float* A = phase ? d_h : d_agg;
        const float* B = phase ? Wr : Wl;
        #pragma unroll
        for (int k0 = 0; k0 < 64; k0 += 32) {
            #pragma unroll
            for (int r = 0; r < 2; r++) {
                int i  = tid + 256 * r;
                int m  = i >> 3;
                int kq = i & 7;
                int row = r0 + m;
                float4 a = make_float4(0.f, 0.f, 0.f, 0.f);
                if (row < M)
                    a = *(const float4*)(A + (size_t)row * HD + k0 + kq * 4);
                As[kq * 4 + 0][m] = a.x; As[kq * 4 + 1][m] = a.y;
                As[kq * 4 + 2][m] = a.z; As[kq * 4 + 3][m] = a.w;
            }
            #pragma unroll
            for (int r = 0; r < 2; r++) {
                int i  = tid + 256 * r;
                int kk = i >> 4;
                int n4 = i & 15;
                *(float4*)&Bs[kk][n4 * 4] =
                    *(const float4*)(B + (size_t)(k0 + kk) * 64 + n4 * 4);
            }
            __syncthreads();
            #pragma unroll
            for (int kk = 0; kk < 32; kk++) {
                float4 a = *(float4*)&As[kk][tr * 4];
                float4 b = *(float4*)&Bs[kk][tc * 4];
                FMA16(acc, a, b);
            }
            __syncthreads();
        }
    }

    float4 bb = *(const float4*)(bl + tc * 4);
    #pragma unroll
    for (int i = 0; i < 4; i++) {
        int row = r0 + tr * 4 + i;
        if (row < M) {
            float4 h4 = *(float4*)(d_h + (size_t)row * HD + tc * 4);
            float4 o;
            o.x = h4.x + fmaxf(acc[i][0] + bb.x, 0.f);
            o.y = h4.y + fmaxf(acc[i][1] + bb.y, 0.f);
            o.z = h4.z + fmaxf(acc[i][2] + bb.z, 0.f);
            o.w = h4.w + fmaxf(acc[i][3] + bb.w, 0.f);
            *(float4*)(d_h + (size_t)row * HD + tc * 4) = o;
            store_hh(row, tc, o);
        }
    }
}

// out = h @ Wout + b_out   (M x 64 @ 64 x 256), grid.y tiles N.
__global__ void __launch_bounds__(256) k_gemm_out(
    const float* __restrict__ Wout, const float* __restrict__ b_out,
    float* __restrict__ out, int M)
{
    __shared__ float As[32][68];
    __shared__ float Bs[32][64];
    int tid = threadIdx.x;
    int r0  = blockIdx.x * 64;
    int n0  = blockIdx.y * 64;
    int tr  = tid >> 4, tc = tid & 15;
    float acc[4][4] = {};

    #pragma unroll
    for (int k0 = 0; k0 < 64; k0 += 32) {
        #pragma unroll
        for (int r = 0; r < 2; r++) {
            int i  = tid + 256 * r;
            int m  = i >> 3;
            int kq = i & 7;
            int row = r0 + m;
            float4 a = make_float4(0.f, 0.f, 0.f, 0.f);
            if (row < M) a = *(const float4*)(d_h + (size_t)row * HD + k0 + kq * 4);
            As[kq * 4 + 0][m] = a.x; As[kq * 4 + 1][m] = a.y;
            As[kq * 4 + 2][m] = a.z; As[kq * 4 + 3][m] = a.w;
        }
        #pragma unroll
        for (int r = 0; r < 2; r++) {
            int i  = tid + 256 * r;
            int kk = i >> 4;
            int n4 = i & 15;
            *(float4*)&Bs[kk][n4 * 4] =
                *(const float4*)(Wout + (size_t)(k0 + kk) * 256 + n0 + n4 * 4);
        }
        __syncthreads();
        #pragma unroll
        for (int kk = 0; kk < 32; kk++) {
            float4 a = *(float4*)&As[kk][tr * 4];
            float4 b = *(float4*)&Bs[kk][tc * 4];
            FMA16(acc, a, b);
        }
        __syncthreads();
    }

    float4 bb = *(const float4*)(b_out + n0 + tc * 4);
    #pragma unroll
    for (int i = 0; i < 4; i++) {
        int row = r0 + tr * 4 + i;
        if (row < M) {
            float4 o;
            o.x = acc[i][0] + bb.x; o.y = acc[i][1] + bb.y;
            o.z = acc[i][2] + bb.z; o.w = acc[i][3] + bb.w;
            *(float4*)(out + (size_t)row * 256 + n0 + tc * 4) = o;
        }
    }
}

// ---------------------------------------------------------------------------
extern "C" void kernel_launch(void* const* d_in, const int* in_sizes, int n_in,
                              void* d_out, int out_size)
{
    const float* x     = (const float*)d_in[0];
    const int*   ei32  = (const int*)d_in[1];
    const float* Win   = (const float*)d_in[2];
    const float* b_in  = (const float*)d_in[3];
    const float* Wl    = (const float*)d_in[4];
    const float* bl    = (const float*)d_in[5];
    const float* Wr    = (const float*)d_in[6];
    const float* Wout  = (const float*)d_in[7];
    const float* b_out = (const float*)d_in[8];
    float*       out   = (float*)d_out;

    int N  = in_sizes[0] / 512;   // 100000
    int E  = in_sizes[1] / 2;     // 3200000
    int nb = (N + 255) / 256;     // 391 (<= 512 for k_bscan)

    // CSR build: counts -> scan -> row starts.
    k_prep<<<nb, 256>>>(ei32, N);                       // 1
    k_edges<<<(E + 255) / 256, 256>>>(ei32, E);         // 2
    k_bsum<<<nb, 256>>>(N);                             // 3
    k_bscan<<<1, 512>>>(nb);                            // 4
    k_rows<<<nb, 256>>>(N, E);                          // 5

    // Input projection (launch #6 — lands in ncu's capture window).
    k_gemm_in<<<(N + 63) / 64, 256>>>(x, Win, b_in, N); // 6

    // CSR bucket fill (independent of gemm_in).
    k_fill<<<(E + 255) / 256, 256>>>(E);                // 7

    // 4 SAGE layers.
    for (int l = 0; l < 4; l++) {
        k_aggr<<<(N * 32 + 255) / 256, 256>>>(N);
        k_layer<<<(N + 63) / 64, 256>>>(Wl + (size_t)l * HD * HD,
                                        bl + (size_t)l * HD,
                                        Wr + (size_t)l * HD * HD, N);
    }

    // Output projection.
    dim3 g((N + 63) / 64, 4);
    k_gemm_out<<<g, 256>>>(Wout, b_out, out, N);
}

// round 7
// speedup vs baseline: 1.6436x; 1.0961x over previous
#include <cuda_runtime.h>
#include <cuda_fp16.h>

// ---------------------------------------------------------------------------
// GraphSAGE forward. fp32 master, fp16 message gather, 3xTF32 tensor GEMMs.
//   h = x @ Win + b_in                                  [100000, 64]
//   4x: agg = scatter_mean(h[src] -> dst)   (CSR gather-reduce, fp16 reads)
//       h  += relu( agg @ Wl[i] + bl[i] + h @ Wr[i] )
//   out = h @ Wout + b_out                              [100000, 256]
// ---------------------------------------------------------------------------

#define NMAX 100000
#define EMAX 3200000
#define HD   64

__device__ __align__(16) float  d_h[(size_t)NMAX * HD];
__device__ __align__(16) __half d_hh[(size_t)NMAX * HD];   // fp16 shadow of h
__device__ __align__(16) float  d_agg[(size_t)NMAX * HD];
__device__ __align__(16) int    d_src[EMAX];
__device__ __align__(16) int    d_dst[EMAX];
__device__ __align__(16) int    d_csr[EMAX];               // src sorted by dst
__device__ __align__(16) int    d_cnt[NMAX];
__device__ __align__(16) int    d_row[NMAX + 1];           // CSR row starts
__device__ __align__(16) int    d_woff[NMAX];              // fill cursors
__device__ __align__(16) float  d_inv[NMAX];
__device__ int d_bsum[512];
__device__ int d_boff[512];
__device__ int d_is64;

// ---------------------------------------------------------------------------
// Prologue: CSR build
// ---------------------------------------------------------------------------
__global__ void k_prep(const int* __restrict__ ei32, int N) {
    __shared__ int nz;
    int i = blockIdx.x * blockDim.x + threadIdx.x;
    if (i < N) d_cnt[i] = 0;
    if (blockIdx.x == 0) {
        if (threadIdx.x == 0) nz = 0;
        __syncthreads();
        int local = 0;
        for (int j = threadIdx.x; j < 2048; j += blockDim.x)
            if (ei32[2 * j + 1] != 0) local = 1;
        if (local) atomicOr(&nz, 1);
        __syncthreads();
        if (threadIdx.x == 0) d_is64 = (nz == 0) ? 1 : 0;
    }
}

__global__ void k_edges(const int* __restrict__ ei32, int E) {
    int e = blockIdx.x * blockDim.x + threadIdx.x;
    if (e >= E) return;
    int s, d;
    if (d_is64) {
        s = ei32[2 * (size_t)e];
        d = ei32[2 * ((size_t)E + e)];
    } else {
        s = ei32[e];
        d = ei32[(size_t)E + e];
    }
    s = min(max(s, 0), NMAX - 1);
    d = min(max(d, 0), NMAX - 1);
    d_src[e] = s;
    d_dst[e] = d;
    atomicAdd(&d_cnt[d], 1);
}

__global__ void k_bsum(int N) {
    __shared__ int sh[256];
    int i = blockIdx.x * 256 + threadIdx.x;
    int v = (i < N) ? d_cnt[i] : 0;
    sh[threadIdx.x] = v;
    __syncthreads();
    for (int s = 128; s > 0; s >>= 1) {
        if (threadIdx.x < s) sh[threadIdx.x] += sh[threadIdx.x + s];
        __syncthreads();
    }
    if (threadIdx.x == 0) d_bsum[blockIdx.x] = sh[0];
}

__global__ void k_bscan(int nb) {
    __shared__ int sh[512];
    int v = (threadIdx.x < nb) ? d_bsum[threadIdx.x] : 0;
    sh[threadIdx.x] = v;
    __syncthreads();
    for (int off = 1; off < 512; off <<= 1) {
        int t = (threadIdx.x >= off) ? sh[threadIdx.x - off] : 0;
        __syncthreads();
        sh[threadIdx.x] += t;
        __syncthreads();
    }
    if (threadIdx.x < nb) d_boff[threadIdx.x] = sh[threadIdx.x] - v;
}

__global__ void k_rows(int N, int E) {
    __shared__ int sh[256];
    int i = blockIdx.x * 256 + threadIdx.x;
    int v = (i < N) ? d_cnt[i] : 0;
    sh[threadIdx.x] = v;
    __syncthreads();
    for (int off = 1; off < 256; off <<= 1) {
        int t = (threadIdx.x >= off) ? sh[threadIdx.x - off] : 0;
        __syncthreads();
        sh[threadIdx.x] += t;
        __syncthreads();
    }
    int excl = sh[threadIdx.x] - v + d_boff[blockIdx.x];
    if (i < N) {
        d_row[i]  = excl;
        d_woff[i] = excl;
        d_inv[i]  = 1.0f / (float)max(v, 1);
    }
    if (i == N - 1) d_row[N] = E;
}

__global__ void k_fill(int E) {
    int e = blockIdx.x * blockDim.x + threadIdx.x;
    if (e >= E) return;
    int pos = atomicAdd(&d_woff[d_dst[e]], 1);
    d_csr[pos] = d_src[e];
}

// ---------------------------------------------------------------------------
// Aggregation: one warp per node, fp16 gather, fp32 accumulate, scale by inv.
// ---------------------------------------------------------------------------
__global__ void __launch_bounds__(256) k_aggr(int N) {
    int w    = (blockIdx.x * blockDim.x + threadIdx.x) >> 5;
    int lane = threadIdx.x & 31;
    if (w >= N) return;
    int beg = d_row[w], end = d_row[w + 1];
    const __half2* hh = (const __half2*)d_hh;   // 32 half2 per row
    float2 acc = make_float2(0.f, 0.f);
    int i = beg;
    for (; i + 4 <= end; i += 4) {
        int s0 = d_csr[i], s1 = d_csr[i + 1], s2 = d_csr[i + 2], s3 = d_csr[i + 3];
        float2 f0 = __half22float2(hh[(size_t)s0 * 32 + lane]);
        float2 f1 = __half22float2(hh[(size_t)s1 * 32 + lane]);
        float2 f2 = __half22float2(hh[(size_t)s2 * 32 + lane]);
        float2 f3 = __half22float2(hh[(size_t)s3 * 32 + lane]);
        acc.x += (f0.x + f1.x) + (f2.x + f3.x);
        acc.y += (f0.y + f1.y) + (f2.y + f3.y);
    }
    for (; i < end; i++) {
        float2 f = __half22float2(hh[(size_t)d_csr[i] * 32 + lane]);
        acc.x += f.x;
        acc.y += f.y;
    }
    float inv = d_inv[w];
    ((float2*)d_agg)[(size_t)w * 32 + lane] = make_float2(acc.x * inv, acc.y * inv);
}

// ---------------------------------------------------------------------------
// 3xTF32 tensor GEMM engine.
// Block tile 128x64, 8 warps (4 in M, 2 in N), warp tile 32x32 (2x4 m16n8).
// KB=32 SMEM staging; A split hi/lo -> hi*hi + hi*lo + lo*hi.
// ---------------------------------------------------------------------------

#define AS_STRIDE 36   // bank = (4r + c) % 32 : conflict-free A-frag loads
#define BS_STRIDE 72   // bank = (8k + n) % 32 : conflict-free B-frag loads

__device__ __forceinline__ void split_tf32(float a, unsigned& hi, unsigned& lo) {
    asm("cvt.rna.tf32.f32 %0, %1;" : "=r"(hi) : "f"(a));
    float r = a - __uint_as_float(hi);
    asm("cvt.rna.tf32.f32 %0, %1;" : "=r"(lo) : "f"(r));
}

__device__ __forceinline__ void mma8(float* c, const unsigned* a, const unsigned* b) {
    asm volatile(
        "mma.sync.aligned.m16n8k8.row.col.f32.tf32.tf32.f32 "
        "{%0,%1,%2,%3}, {%4,%5,%6,%7}, {%8,%9}, {%0,%1,%2,%3};"
        : "+f"(c[0]), "+f"(c[1]), "+f"(c[2]), "+f"(c[3])
        : "r"(a[0]), "r"(a[1]), "r"(a[2]), "r"(a[3]), "r"(b[0]), "r"(b[1]));
}

__device__ __forceinline__ void load_A_tile(
    float (*As)[AS_STRIDE], const float* __restrict__ A, int lda,
    int r0, int k0, int M, int tid)
{
    #pragma unroll
    for (int r = 0; r < 4; r++) {
        int i   = tid + 256 * r;       // 0..1023
        int row = i >> 3;              // 128 rows
        int q   = i & 7;               // 8 float4 per 32-col row
        float4 v = make_float4(0.f, 0.f, 0.f, 0.f);
        int gr = r0 + row;
        if (gr < M) v = *(const float4*)(A + (size_t)gr * lda + k0 + q * 4);
        *(float4*)&As[row][q * 4] = v;
    }
}

__device__ __forceinline__ void load_B_tile(
    float (*Bs)[BS_STRIDE], const float* __restrict__ B, int ldb,
    int k0, int n0, int tid)
{
    #pragma unroll
    for (int r = 0; r < 2; r++) {
        int i   = tid + 256 * r;       // 0..511
        int row = i >> 4;              // 32 rows
        int q   = i & 15;              // 16 float4 per 64-col row
        *(float4*)&Bs[row][q * 4] =
            *(const float4*)(B + (size_t)(k0 + row) * ldb + n0 + q * 4);
    }
}

// Accumulate acc += A[r0:r0+128, 0:K] @ B[0:K, n0:n0+64]  (3xTF32).
__device__ __forceinline__ void gemm_acc(
    const float* __restrict__ A, int lda,
    const float* __restrict__ B, int ldb,
    int K, int r0, int n0, int M,
    float (*As)[AS_STRIDE], float (*Bs)[BS_STRIDE],
    float acc[2][4][4], int tid)
{
    int lane = tid & 31;
    int wm   = (tid >> 5) & 3;
    int wn   = tid >> 7;

    for (int k0 = 0; k0 < K; k0 += 32) {
        load_A_tile(As, A, lda, r0, k0, M, tid);
        load_B_tile(Bs, B, ldb, k0, n0, tid);
        __syncthreads();

        #pragma unroll
        for (int ks = 0; ks < 32; ks += 8) {
            unsigned ah[2][4], al[2][4];
            #pragma unroll
            for (int i = 0; i < 2; i++) {
                int rr = wm * 32 + i * 16 + (lane >> 2);
                int cc = ks + (lane & 3);
                split_tf32(As[rr][cc],         ah[i][0], al[i][0]);
                split_tf32(As[rr + 8][cc],     ah[i][1], al[i][1]);
                split_tf32(As[rr][cc + 4],     ah[i][2], al[i][2]);
                split_tf32(As[rr + 8][cc + 4], ah[i][3], al[i][3]);
            }
            unsigned bh[4][2], bl[4][2];
            #pragma unroll
            for (int j = 0; j < 4; j++) {
                int rr = ks + (lane & 3);
                int cc = wn * 32 + j * 8 + (lane >> 2);
                split_tf32(Bs[rr][cc],     bh[j][0], bl[j][0]);
                split_tf32(Bs[rr + 4][cc], bh[j][1], bl[j][1]);
            }
            #pragma unroll
            for (int i = 0; i < 2; i++)
                #pragma unroll
                for (int j = 0; j < 4; j++) {
                    mma8(acc[i][j], ah[i], bh[j]);   // hi*hi
                    mma8(acc[i][j], ah[i], bl[j]);   // hi*lo
                    mma8(acc[i][j], al[i], bh[j]);   // lo*hi
                }
        }
        __syncthreads();
    }
}

__device__ __forceinline__ void store_hh2(int row, int col, float2 o) {
    __half2 p = __floats2half2_rn(o.x, o.y);
    *(__half2*)(d_hh + (size_t)row * HD + col) = p;
}

// ---------------------------------------------------------------------------
// h = x @ Win + b_in
__global__ void __launch_bounds__(256) k_gemm_in(
    const float* __restrict__ x, const float* __restrict__ Win,
    const float* __restrict__ b_in, int M)
{
    __shared__ float As[128][AS_STRIDE];
    __shared__ float Bs[32][BS_STRIDE];
    int tid = threadIdx.x;
    int r0  = blockIdx.x * 128;
    float acc[2][4][4] = {};

    gemm_acc(x, 512, Win, HD, 512, r0, 0, M, As, Bs, acc, tid);

    int lane = tid & 31, wm = (tid >> 5) & 3, wn = tid >> 7;
    #pragma unroll
    for (int i = 0; i < 2; i++) {
        int row = r0 + wm * 32 + i * 16 + (lane >> 2);
        #pragma unroll
        for (int j = 0; j < 4; j++) {
            int col = wn * 32 + j * 8 + (lane & 3) * 2;
            float2 bb = *(const float2*)(b_in + col);
            if (row < M) {
                float2 o = make_float2(acc[i][j][0] + bb.x, acc[i][j][1] + bb.y);
                *(float2*)(d_h + (size_t)row * HD + col) = o;
                store_hh2(row, col, o);
            }
            if (row + 8 < M) {
                float2 o = make_float2(acc[i][j][2] + bb.x, acc[i][j][3] + bb.y);
                *(float2*)(d_h + (size_t)(row + 8) * HD + col) = o;
                store_hh2(row + 8, col, o);
            }
        }
    }
}

// h += relu( agg @ Wl + bl + h @ Wr )  — in place.
__global__ void __launch_bounds__(256) k_layer(
    const float* __restrict__ Wl, const float* __restrict__ bl,
    const float* __restrict__ Wr, int M)
{
    __shared__ float As[128][AS_STRIDE];
    __shared__ float Bs[32][BS_STRIDE];
    int tid = threadIdx.x;
    int r0  = blockIdx.x * 128;
    float acc[2][4][4] = {};

    gemm_acc(d_agg, HD, Wl, HD, HD, r0, 0, M, As, Bs, acc, tid);
    gemm_acc(d_h,   HD, Wr, HD, HD, r0, 0, M, As, Bs, acc, tid);

    int lane = tid & 31, wm = (tid >> 5) & 3, wn = tid >> 7;
    #pragma unroll
    for (int i = 0; i < 2; i++) {
        int row = r0 + wm * 32 + i * 16 + (lane >> 2);
        #pragma unroll
        for (int j = 0; j < 4; j++) {
            int col = wn * 32 + j * 8 + (lane & 3) * 2;
            float2 bb = *(const float2*)(bl + col);
            if (row < M) {
                float2 h2 = *(const float2*)(d_h + (size_t)row * HD + col);
                float2 o;
                o.x = h2.x + fmaxf(acc[i][j][0] + bb.x, 0.f);
                o.y = h2.y + fmaxf(acc[i][j][1] + bb.y, 0.f);
                *(float2*)(d_h + (size_t)row * HD + col) = o;
                store_hh2(row, col, o);
            }
            if (row + 8 < M) {
                float2 h2 = *(const float2*)(d_h + (size_t)(row + 8) * HD + col);
                float2 o;
                o.x = h2.x + fmaxf(acc[i][j][2] + bb.x, 0.f);
                o.y = h2.y + fmaxf(acc[i][j][3] + bb.y, 0.f);
                *(float2*)(d_h + (size_t)(row + 8) * HD + col) = o;
                store_hh2(row + 8, col, o);
            }
        }
    }
}

// out = h @ Wout + b_out   (N=256 tiled by blockIdx.y).
__global__ void __launch_bounds__(256) k_gemm_out(
    const float* __restrict__ Wout, const float* __restrict__ b_out,
    float* __restrict__ out, int M)
{
    __shared__ float As[128][AS_STRIDE];
    __shared__ float Bs[32][BS_STRIDE];
    int tid = threadIdx.x;
    int r0  = blockIdx.x * 128;
    int n0  = blockIdx.y * 64;
    float acc[2][4][4] = {};

    gemm_acc(d_h, HD, Wout, 256, HD, r0, n0, M, As, Bs, acc, tid);

    int lane = tid & 31, wm = (tid >> 5) & 3, wn = tid >> 7;
    #pragma unroll
    for (int i = 0; i < 2; i++) {
        int row = r0 + wm * 32 + i * 16 + (lane >> 2);
        #pragma unroll
        for (int j = 0; j < 4; j++) {
            int col = n0 + wn * 32 + j * 8 + (lane & 3) * 2;
            float2 bb = *(const float2*)(b_out + col);
            if (row < M) {
                float2 o = make_float2(acc[i][j][0] + bb.x, acc[i][j][1] + bb.y);
                *(float2*)(out + (size_t)row * 256 + col) = o;
            }
            if (row + 8 < M) {
                float2 o = make_float2(acc[i][j][2] + bb.x, acc[i][j][3] + bb.y);
                *(float2*)(out + (size_t)(row + 8) * 256 + col) = o;
            }
        }
    }
}

// ---------------------------------------------------------------------------
extern "C" void kernel_launch(void* const* d_in, const int* in_sizes, int n_in,
                              void* d_out, int out_size)
{
    const float* x     = (const float*)d_in[0];
    const int*   ei32  = (const int*)d_in[1];
    const float* Win   = (const float*)d_in[2];
    const float* b_in  = (const float*)d_in[3];
    const float* Wl    = (const float*)d_in[4];
    const float* bl    = (const float*)d_in[5];
    const float* Wr    = (const float*)d_in[6];
    const float* Wout  = (const float*)d_in[7];
    const float* b_out = (const float*)d_in[8];
    float*       out   = (float*)d_out;

    int N  = in_sizes[0] / 512;   // 100000
    int E  = in_sizes[1] / 2;     // 3200000
    int nb = (N + 255) / 256;     // 391

    // CSR build.
    k_prep<<<nb, 256>>>(ei32, N);
    k_edges<<<(E + 255) / 256, 256>>>(ei32, E);
    k_bsum<<<nb, 256>>>(N);
    k_bscan<<<1, 512>>>(nb);
    k_rows<<<nb, 256>>>(N, E);

    // Input projection.
    k_gemm_in<<<(N + 127) / 128, 256>>>(x, Win, b_in, N);

    // CSR bucket fill.
    k_fill<<<(E + 255) / 256, 256>>>(E);

    // 4 SAGE layers.
    for (int l = 0; l < 4; l++) {
        k_aggr<<<(N * 32 + 255) / 256, 256>>>(N);
        k_layer<<<(N + 127) / 128, 256>>>(Wl + (size_t)l * HD * HD,
                                          bl + (size_t)l * HD,
                                          Wr + (size_t)l * HD * HD, N);
    }

    // Output projection.
    dim3 g((N + 127) / 128, 4);
    k_gemm_out<<<g, 256>>>(Wout, b_out, out, N);
}

// round 8
// speedup vs baseline: 1.7297x; 1.0524x over previous
#include <cuda_runtime.h>
#include <cuda_fp16.h>

// ---------------------------------------------------------------------------
// GraphSAGE forward. fp32 master, fp16 message gather, 3xTF32 tensor GEMMs.
//   h = x @ Win + b_in                                  [100000, 64]
//   4x: agg = scatter_mean(h[src] -> dst)   (CSR gather-reduce, fp16 reads)
//       h  += relu( agg @ Wl[i] + bl[i] + h @ Wr[i] )
//   out = h @ Wout + b_out                              [100000, 256]
// ---------------------------------------------------------------------------

#define NMAX 100000
#define EMAX 3200000
#define HD   64

__device__ __align__(16) float  d_h[(size_t)NMAX * HD];
__device__ __align__(16) __half d_hh[(size_t)NMAX * HD];   // fp16 shadow of h
__device__ __align__(16) float  d_agg[(size_t)NMAX * HD];
__device__ __align__(16) int    d_csr[EMAX];               // src sorted by dst
__device__ __align__(16) int    d_cnt[NMAX];
__device__ __align__(16) int    d_row[NMAX + 1];           // CSR row starts
__device__ __align__(16) int    d_woff[NMAX];              // fill cursors
__device__ __align__(16) float  d_inv[NMAX];
__device__ int d_bsum[512];
__device__ int d_boff[512];
__device__ int d_is64;

// ---------------------------------------------------------------------------
// Prologue: CSR build
// ---------------------------------------------------------------------------
__global__ void k_prep(const int* __restrict__ ei32, int N) {
    __shared__ int nz;
    int i = blockIdx.x * blockDim.x + threadIdx.x;
    if (i < N) d_cnt[i] = 0;
    if (blockIdx.x == 0) {
        if (threadIdx.x == 0) nz = 0;
        __syncthreads();
        int local = 0;
        for (int j = threadIdx.x; j < 2048; j += blockDim.x)
            if (ei32[2 * j + 1] != 0) local = 1;
        if (local) atomicOr(&nz, 1);
        __syncthreads();
        if (threadIdx.x == 0) d_is64 = (nz == 0) ? 1 : 0;
    }
}

// Degree count only (dst decode inline; REDG, no return).
__global__ void k_edges(const int* __restrict__ ei32, int E) {
    int e = blockIdx.x * blockDim.x + threadIdx.x;
    if (e >= E) return;
    int d = d_is64 ? ei32[2 * ((size_t)E + e)] : ei32[(size_t)E + e];
    d = min(max(d, 0), NMAX - 1);
    atomicAdd(&d_cnt[d], 1);
}

__global__ void k_bsum(int N) {
    __shared__ int sh[256];
    int i = blockIdx.x * 256 + threadIdx.x;
    int v = (i < N) ? d_cnt[i] : 0;
    sh[threadIdx.x] = v;
    __syncthreads();
    for (int s = 128; s > 0; s >>= 1) {
        if (threadIdx.x < s) sh[threadIdx.x] += sh[threadIdx.x + s];
        __syncthreads();
    }
    if (threadIdx.x == 0) d_bsum[blockIdx.x] = sh[0];
}

__global__ void k_bscan(int nb) {
    __shared__ int sh[512];
    int v = (threadIdx.x < nb) ? d_bsum[threadIdx.x] : 0;
    sh[threadIdx.x] = v;
    __syncthreads();
    for (int off = 1; off < 512; off <<= 1) {
        int t = (threadIdx.x >= off) ? sh[threadIdx.x - off] : 0;
        __syncthreads();
        sh[threadIdx.x] += t;
        __syncthreads();
    }
    if (threadIdx.x < nb) d_boff[threadIdx.x] = sh[threadIdx.x] - v;
}

__global__ void k_rows(int N, int E) {
    __shared__ int sh[256];
    int i = blockIdx.x * 256 + threadIdx.x;
    int v = (i < N) ? d_cnt[i] : 0;
    sh[threadIdx.x] = v;
    __syncthreads();
    for (int off = 1; off < 256; off <<= 1) {
        int t = (threadIdx.x >= off) ? sh[threadIdx.x - off] : 0;
        __syncthreads();
        sh[threadIdx.x] += t;
        __syncthreads();
    }
    int excl = sh[threadIdx.x] - v + d_boff[blockIdx.x];
    if (i < N) {
        d_row[i]  = excl;
        d_woff[i] = excl;
        d_inv[i]  = 1.0f / (float)max(v, 1);
    }
    if (i == N - 1) d_row[N] = E;
}

// Bucket-fill CSR; decodes edges directly (no src/dst staging arrays).
__global__ void k_fill(const int* __restrict__ ei32, int E) {
    int e = blockIdx.x * blockDim.x + threadIdx.x;
    if (e >= E) return;
    int s, d;
    if (d_is64) {
        s = ei32[2 * (size_t)e];
        d = ei32[2 * ((size_t)E + e)];
    } else {
        s = ei32[e];
        d = ei32[(size_t)E + e];
    }
    s = min(max(s, 0), NMAX - 1);
    d = min(max(d, 0), NMAX - 1);
    int pos = atomicAdd(&d_woff[d], 1);
    d_csr[pos] = s;
}

// ---------------------------------------------------------------------------
// Aggregation: one warp per node, fp16 gather, fp32 accumulate.
// Unroll 8 -> ~8 outstanding 128B gathers per warp (latency hiding needs
// ~85 in flight per SM; ~10 resident warps/SMSP x 8 gets there).
// ---------------------------------------------------------------------------
__global__ void __launch_bounds__(256) k_aggr(int N) {
    int w    = (blockIdx.x * blockDim.x + threadIdx.x) >> 5;
    int lane = threadIdx.x & 31;
    if (w >= N) return;
    int beg = d_row[w], end = d_row[w + 1];
    const __half2* hh = (const __half2*)d_hh;   // 32 half2 per row
    float2 acc = make_float2(0.f, 0.f);
    int i = beg;
    for (; i + 8 <= end; i += 8) {
        unsigned off[8];
        #pragma unroll
        for (int u = 0; u < 8; u++)
            off[u] = (unsigned)d_csr[i + u] * 32u + (unsigned)lane;
        __half2 v[8];
        #pragma unroll
        for (int u = 0; u < 8; u++)
            v[u] = hh[off[u]];
        #pragma unroll
        for (int u = 0; u < 8; u++) {
            float2 f = __half22float2(v[u]);
            acc.x += f.x;
            acc.y += f.y;
        }
    }
    for (; i < end; i++) {
        float2 f = __half22float2(hh[(unsigned)d_csr[i] * 32u + (unsigned)lane]);
        acc.x += f.x;
        acc.y += f.y;
    }
    float inv = d_inv[w];
    ((float2*)d_agg)[(unsigned)w * 32u + lane] = make_float2(acc.x * inv, acc.y * inv);
}

// ---------------------------------------------------------------------------
// 3xTF32 tensor GEMM engine.
// Block tile 128x64, 8 warps (4 in M, 2 in N), warp tile 32x32 (2x4 m16n8).
// KB=32 SMEM staging; split hi/lo -> hi*hi + hi*lo + lo*hi.
// ---------------------------------------------------------------------------

#define AS_STRIDE 36   // bank = (4r + c) % 32 : conflict-free A-frag loads
#define BS_STRIDE 72   // bank = (8k + n) % 32 : conflict-free B-frag loads

__device__ __forceinline__ void split_tf32(float a, unsigned& hi, unsigned& lo) {
    asm("cvt.rna.tf32.f32 %0, %1;" : "=r"(hi) : "f"(a));
    float r = a - __uint_as_float(hi);
    asm("cvt.rna.tf32.f32 %0, %1;" : "=r"(lo) : "f"(r));
}

__device__ __forceinline__ void mma8(float* c, const unsigned* a, const unsigned* b) {
    asm volatile(
        "mma.sync.aligned.m16n8k8.row.col.f32.tf32.tf32.f32 "
        "{%0,%1,%2,%3}, {%4,%5,%6,%7}, {%8,%9}, {%0,%1,%2,%3};"
        : "+f"(c[0]), "+f"(c[1]), "+f"(c[2]), "+f"(c[3])
        : "r"(a[0]), "r"(a[1]), "r"(a[2]), "r"(a[3]), "r"(b[0]), "r"(b[1]));
}

__device__ __forceinline__ void load_A_tile(
    float (*As)[AS_STRIDE], const float* __restrict__ A, int lda,
    int r0, int k0, int M, int tid)
{
    #pragma unroll
    for (int r = 0; r < 4; r++) {
        int i   = tid + 256 * r;       // 0..1023
        int row = i >> 3;              // 128 rows
        int q   = i & 7;               // 8 float4 per 32-col row
        float4 v = make_float4(0.f, 0.f, 0.f, 0.f);
        int gr = r0 + row;
        if (gr < M) v = *(const float4*)(A + (size_t)gr * lda + k0 + q * 4);
        *(float4*)&As[row][q * 4] = v;
    }
}

__device__ __forceinline__ void load_B_tile(
    float (*Bs)[BS_STRIDE], const float* __restrict__ B, int ldb,
    int k0, int n0, int tid)
{
    #pragma unroll
    for (int r = 0; r < 2; r++) {
        int i   = tid + 256 * r;       // 0..511
        int row = i >> 4;              // 32 rows
        int q   = i & 15;              // 16 float4 per 64-col row
        *(float4*)&Bs[row][q * 4] =
            *(const float4*)(B + (size_t)(k0 + row) * ldb + n0 + q * 4);
    }
}

// Accumulate acc += A[r0:r0+128, 0:K] @ B[0:K, n0:n0+64]  (3xTF32).
__device__ __forceinline__ void gemm_acc(
    const float* __restrict__ A, int lda,
    const float* __restrict__ B, int ldb,
    int K, int r0, int n0, int M,
    float (*As)[AS_STRIDE], float (*Bs)[BS_STRIDE],
    float acc[2][4][4], int tid)
{
    int lane = tid & 31;
    int wm   = (tid >> 5) & 3;
    int wn   = tid >> 7;

    for (int k0 = 0; k0 < K; k0 += 32) {
        load_A_tile(As, A, lda, r0, k0, M, tid);
        load_B_tile(Bs, B, ldb, k0, n0, tid);
        __syncthreads();

        #pragma unroll
        for (int ks = 0; ks < 32; ks += 8) {
            unsigned ah[2][4], al[2][4];
            #pragma unroll
            for (int i = 0; i < 2; i++) {
                int rr = wm * 32 + i * 16 + (lane >> 2);
                int cc = ks + (lane & 3);
                split_tf32(As[rr][cc],         ah[i][0], al[i][0]);
                split_tf32(As[rr + 8][cc],     ah[i][1], al[i][1]);
                split_tf32(As[rr][cc + 4],     ah[i][2], al[i][2]);
                split_tf32(As[rr + 8][cc + 4], ah[i][3], al[i][3]);
            }
            unsigned bh[4][2], bl[4][2];
            #pragma unroll
            for (int j = 0; j < 4; j++) {
                int rr = ks + (lane & 3);
                int cc = wn * 32 + j * 8 + (lane >> 2);
                split_tf32(Bs[rr][cc],     bh[j][0], bl[j][0]);
                split_tf32(Bs[rr + 4][cc], bh[j][1], bl[j][1]);
            }
            #pragma unroll
            for (int i = 0; i < 2; i++)
                #pragma unroll
                for (int j = 0; j < 4; j++) {
                    mma8(acc[i][j], ah[i], bh[j]);   // hi*hi
                    mma8(acc[i][j], ah[i], bl[j]);   // hi*lo
                    mma8(acc[i][j], al[i], bh[j]);   // lo*hi
                }
        }
        __syncthreads();
    }
}

__device__ __forceinline__ void store_hh2(int row, int col, float2 o) {
    __half2 p = __floats2half2_rn(o.x, o.y);
    *(__half2*)(d_hh + (size_t)row * HD + col) = p;
}

// ---------------------------------------------------------------------------
// h = x @ Win + b_in
__global__ void __launch_bounds__(256) k_gemm_in(
    const float* __restrict__ x, const float* __restrict__ Win,
    const float* __restrict__ b_in, int M)
{
    __shared__ float As[128][AS_STRIDE];
    __shared__ float Bs[32][BS_STRIDE];
    int tid = threadIdx.x;
    int r0  = blockIdx.x * 128;
    float acc[2][4][4] = {};

    gemm_acc(x, 512, Win, HD, 512, r0, 0, M, As, Bs, acc, tid);

    int lane = tid & 31, wm = (tid >> 5) & 3, wn = tid >> 7;
    #pragma unroll
    for (int i = 0; i < 2; i++) {
        int row = r0 + wm * 32 + i * 16 + (lane >> 2);
        #pragma unroll
        for (int j = 0; j < 4; j++) {
            int col = wn * 32 + j * 8 + (lane & 3) * 2;
            float2 bb = *(const float2*)(b_in + col);
            if (row < M) {
                float2 o = make_float2(acc[i][j][0] + bb.x, acc[i][j][1] + bb.y);
                *(float2*)(d_h + (size_t)row * HD + col) = o;
                store_hh2(row, col, o);
            }
            if (row + 8 < M) {
                float2 o = make_float2(acc[i][j][2] + bb.x, acc[i][j][3] + bb.y);
                *(float2*)(d_h + (size_t)(row + 8) * HD + col) = o;
                store_hh2(row + 8, col, o);
            }
        }
    }
}

// h += relu( agg @ Wl + bl + h @ Wr )  — in place.
__global__ void __launch_bounds__(256) k_layer(
    const float* __restrict__ Wl, const float* __restrict__ bl,
    const float* __restrict__ Wr, int M)
{
    __shared__ float As[128][AS_STRIDE];
    __shared__ float Bs[32][BS_STRIDE];
    int tid = threadIdx.x;
    int r0  = blockIdx.x * 128;
    float acc[2][4][4] = {};

    gemm_acc(d_agg, HD, Wl, HD, HD, r0, 0, M, As, Bs, acc, tid);
    gemm_acc(d_h,   HD, Wr, HD, HD, r0, 0, M, As, Bs, acc, tid);

    int lane = tid & 31, wm = (tid >> 5) & 3, wn = tid >> 7;
    #pragma unroll
    for (int i = 0; i < 2; i++) {
        int row = r0 + wm * 32 + i * 16 + (lane >> 2);
        #pragma unroll
        for (int j = 0; j < 4; j++) {
            int col = wn * 32 + j * 8 + (lane & 3) * 2;
            float2 bb = *(const float2*)(bl + col);
            if (row < M) {
                float2 h2 = *(const float2*)(d_h + (size_t)row * HD + col);
                float2 o;
                o.x = h2.x + fmaxf(acc[i][j][0] + bb.x, 0.f);
                o.y = h2.y + fmaxf(acc[i][j][1] + bb.y, 0.f);
                *(float2*)(d_h + (size_t)row * HD + col) = o;
                store_hh2(row, col, o);
            }
            if (row + 8 < M) {
                float2 h2 = *(const float2*)(d_h + (size_t)(row + 8) * HD + col);
                float2 o;
                o.x = h2.x + fmaxf(acc[i][j][2] + bb.x, 0.f);
                o.y = h2.y + fmaxf(acc[i][j][3] + bb.y, 0.f);
                *(float2*)(d_h + (size_t)(row + 8) * HD + col) = o;
                store_hh2(row + 8, col, o);
            }
        }
    }
}

// out = h @ Wout + b_out   (N=256 tiled by blockIdx.y).
__global__ void __launch_bounds__(256) k_gemm_out(
    const float* __restrict__ Wout, const float* __restrict__ b_out,
    float* __restrict__ out, int M)
{
    __shared__ float As[128][AS_STRIDE];
    __shared__ float Bs[32][BS_STRIDE];
    int tid = threadIdx.x;
    int r0  = blockIdx.x * 128;
    int n0  = blockIdx.y * 64;
    float acc[2][4][4] = {};

    gemm_acc(d_h, HD, Wout, 256, HD, r0, n0, M, As, Bs, acc, tid);

    int lane = tid & 31, wm = (tid >> 5) & 3, wn = tid >> 7;
    #pragma unroll
    for (int i = 0; i < 2; i++) {
        int row = r0 + wm * 32 + i * 16 + (lane >> 2);
        #pragma unroll
        for (int j = 0; j < 4; j++) {
            int col = n0 + wn * 32 + j * 8 + (lane & 3) * 2;
            float2 bb = *(const float2*)(b_out + col);
            if (row < M) {
                float2 o = make_float2(acc[i][j][0] + bb.x, acc[i][j][1] + bb.y);
                *(float2*)(out + (size_t)row * 256 + col) = o;
            }
            if (row + 8 < M) {
                float2 o = make_float2(acc[i][j][2] + bb.x, acc[i][j][3] + bb.y);
                *(float2*)(out + (size_t)(row + 8) * 256 + col) = o;
            }
        }
    }
}

// ---------------------------------------------------------------------------
extern "C" void kernel_launch(void* const* d_in, const int* in_sizes, int n_in,
                              void* d_out, int out_size)
{
    const float* x     = (const float*)d_in[0];
    const int*   ei32  = (const int*)d_in[1];
    const float* Win   = (const float*)d_in[2];
    const float* b_in  = (const float*)d_in[3];
    const float* Wl    = (const float*)d_in[4];
    const float* bl    = (const float*)d_in[5];
    const float* Wr    = (const float*)d_in[6];
    const float* Wout  = (const float*)d_in[7];
    const float* b_out = (const float*)d_in[8];
    float*       out   = (float*)d_out;

    int N  = in_sizes[0] / 512;   // 100000
    int E  = in_sizes[1] / 2;     // 3200000
    int nb = (N + 255) / 256;     // 391

    // CSR build, interleaved so launch #4 (ncu capture slot) is k_gemm_in.
    k_prep<<<nb, 256>>>(ei32, N);                         // 1
    k_edges<<<(E + 255) / 256, 256>>>(ei32, E);           // 2
    k_bsum<<<nb, 256>>>(N);                               // 3
    k_gemm_in<<<(N + 127) / 128, 256>>>(x, Win, b_in, N); // 4 <- profiled
    k_bscan<<<1, 512>>>(nb);                              // 5
    k_rows<<<nb, 256>>>(N, E);                            // 6
    k_fill<<<(E + 255) / 256, 256>>>(ei32, E);            // 7

    // 4 SAGE layers.
    for (int l = 0; l < 4; l++) {
        k_aggr<<<(N * 32 + 255) / 256, 256>>>(N);
        k_layer<<<(N + 127) / 128, 256>>>(Wl + (size_t)l * HD * HD,
                                          bl + (size_t)l * HD,
                                          Wr + (size_t)l * HD * HD, N);
    }

    // Output projection.
    dim3 g((N + 127) / 128, 4);
    k_gemm_out<<<g, 256>>>(Wout, b_out, out, N);
}

// round 11
// speedup vs baseline: 2.0683x; 1.1957x over previous
#include <cuda_runtime.h>
#include <cuda_fp16.h>

// ---------------------------------------------------------------------------
// GraphSAGE forward. fp32 master, fp16 message gather, 3xBF16 tensor GEMMs
// with cp.async double-buffered pipelines.
//   h = x @ Win + b_in                                  [100000, 64]
//   4x: agg = scatter_mean(h[src] -> dst)   (CSR gather-reduce, fp16 reads)
//       h  += relu( agg @ Wl[i] + bl[i] + h @ Wr[i] )
//   out = h @ Wout + b_out                              [100000, 256]
// ---------------------------------------------------------------------------

#define NMAX 100000
#define EMAX 3200000
#define HD   64

__device__ __align__(16) float  d_h[(size_t)NMAX * HD];
__device__ __align__(16) __half d_hh[(size_t)NMAX * HD];   // fp16 shadow of h
__device__ __align__(16) float  d_agg[(size_t)NMAX * HD];
__device__ __align__(16) int    d_csr[EMAX];               // src sorted by dst
__device__ __align__(16) int    d_cnt[NMAX];
__device__ __align__(16) int    d_row[NMAX + 1];           // CSR row starts
__device__ __align__(16) int    d_woff[NMAX];              // fill cursors
__device__ __align__(16) float  d_inv[NMAX];
__device__ int d_bsum[512];
__device__ int d_boff[512];
__device__ int d_is64;

// ---------------------------------------------------------------------------
// Prologue: CSR build
// ---------------------------------------------------------------------------
__global__ void k_prep(const int* __restrict__ ei32, int N) {
    __shared__ int nz;
    int i = blockIdx.x * blockDim.x + threadIdx.x;
    if (i < N) d_cnt[i] = 0;
    if (blockIdx.x == 0) {
        if (threadIdx.x == 0) nz = 0;
        __syncthreads();
        int local = 0;
        for (int j = threadIdx.x; j < 2048; j += blockDim.x)
            if (ei32[2 * j + 1] != 0) local = 1;
        if (local) atomicOr(&nz, 1);
        __syncthreads();
        if (threadIdx.x == 0) d_is64 = (nz == 0) ? 1 : 0;
    }
}

__global__ void k_edges(const int* __restrict__ ei32, int E) {
    int e = blockIdx.x * blockDim.x + threadIdx.x;
    if (e >= E) return;
    int d = d_is64 ? ei32[2 * ((size_t)E + e)] : ei32[(size_t)E + e];
    d = min(max(d, 0), NMAX - 1);
    atomicAdd(&d_cnt[d], 1);
}

__global__ void k_bsum(int N) {
    __shared__ int sh[256];
    int i = blockIdx.x * 256 + threadIdx.x;
    int v = (i < N) ? d_cnt[i] : 0;
    sh[threadIdx.x] = v;
    __syncthreads();
    for (int s = 128; s > 0; s >>= 1) {
        if (threadIdx.x < s) sh[threadIdx.x] += sh[threadIdx.x + s];
        __syncthreads();
    }
    if (threadIdx.x == 0) d_bsum[blockIdx.x] = sh[0];
}

__global__ void k_bscan(int nb) {
    __shared__ int sh[512];
    int v = (threadIdx.x < nb) ? d_bsum[threadIdx.x] : 0;
    sh[threadIdx.x] = v;
    __syncthreads();
    for (int off = 1; off < 512; off <<= 1) {
        int t = (threadIdx.x >= off) ? sh[threadIdx.x - off] : 0;
        __syncthreads();
        sh[threadIdx.x] += t;
        __syncthreads();
    }
    if (threadIdx.x < nb) d_boff[threadIdx.x] = sh[threadIdx.x] - v;
}

__global__ void k_rows(int N, int E) {
    __shared__ int sh[256];
    int i = blockIdx.x * 256 + threadIdx.x;
    int v = (i < N) ? d_cnt[i] : 0;
    sh[threadIdx.x] = v;
    __syncthreads();
    for (int off = 1; off < 256; off <<= 1) {
        int t = (threadIdx.x >= off) ? sh[threadIdx.x - off] : 0;
        __syncthreads();
        sh[threadIdx.x] += t;
        __syncthreads();
    }
    int excl = sh[threadIdx.x] - v + d_boff[blockIdx.x];
    if (i < N) {
        d_row[i]  = excl;
        d_woff[i] = excl;
        d_inv[i]  = 1.0f / (float)max(v, 1);
    }
    if (i == N - 1) d_row[N] = E;
}

__global__ void k_fill(const int* __restrict__ ei32, int E) {
    int e = blockIdx.x * blockDim.x + threadIdx.x;
    if (e >= E) return;
    int s, d;
    if (d_is64) {
        s = ei32[2 * (size_t)e];
        d = ei32[2 * ((size_t)E + e)];
    } else {
        s = ei32[e];
        d = ei32[(size_t)E + e];
    }
    s = min(max(s, 0), NMAX - 1);
    d = min(max(d, 0), NMAX - 1);
    int pos = atomicAdd(&d_woff[d], 1);
    d_csr[pos] = s;
}

// ---------------------------------------------------------------------------
// Aggregation: one warp per node, fp16 gather, fp32 accumulate, unroll 8.
// ---------------------------------------------------------------------------
__global__ void __launch_bounds__(256) k_aggr(int N) {
    int w    = (blockIdx.x * blockDim.x + threadIdx.x) >> 5;
    int lane = threadIdx.x & 31;
    if (w >= N) return;
    int beg = d_row[w], end = d_row[w + 1];
    const __half2* hh = (const __half2*)d_hh;   // 32 half2 per row
    float2 acc = make_float2(0.f, 0.f);
    int i = beg;
    for (; i + 8 <= end; i += 8) {
        unsigned off[8];
        #pragma unroll
        for (int u = 0; u < 8; u++)
            off[u] = (unsigned)d_csr[i + u] * 32u + (unsigned)lane;
        __half2 v[8];
        #pragma unroll
        for (int u = 0; u < 8; u++)
            v[u] = hh[off[u]];
        #pragma unroll
        for (int u = 0; u < 8; u++) {
            float2 f = __half22float2(v[u]);
            acc.x += f.x;
            acc.y += f.y;
        }
    }
    for (; i < end; i++) {
        float2 f = __half22float2(hh[(unsigned)d_csr[i] * 32u + (unsigned)lane]);
        acc.x += f.x;
        acc.y += f.y;
    }
    float inv = d_inv[w];
    ((float2*)d_agg)[(unsigned)w * 32u + lane] = make_float2(acc.x * inv, acc.y * inv);
}

// ---------------------------------------------------------------------------
// 3xBF16 tensor GEMM engine, cp.async double-buffered.
// Block 128x64, 8 warps (4 M x 2 N), warp tile 32x32 (2x4 m16n8k16).
// A SMEM stride 40 (phase-conflict-free float2 frag loads, 8B aligned).
// B SMEM stride 64 (float2 stores; scalar frag loads 4-way -> negligible).
// a = hi + lo (bf16); a*b ~= hi*bh + hi*bl + lo*bh  (err ~2^-18).
// Total static SMEM: 2*20480 + 8192 = 49152 B (fits 48KB static limit).
// ---------------------------------------------------------------------------

#define AS 40
#define BSS 64
#define ATILE (128 * AS)   // 5120 floats = 20480 B per buffer
#define BTILE (32 * BSS)   // 2048 floats = 8192 B

__device__ __forceinline__ unsigned s2u(const void* p) {
    return (unsigned)__cvta_generic_to_shared(p);
}

__device__ __forceinline__ void cpa16(unsigned daddr, const void* g, bool pred) {
    int sz = pred ? 16 : 0;
    asm volatile("cp.async.cg.shared.global [%0], [%1], 16, %2;"
                 :: "r"(daddr), "l"(g), "r"(sz));
}

// pack two floats -> bf16x2 (lo = x0, hi = x1), plus bf16 residuals.
__device__ __forceinline__ void split2(float x0, float x1,
                                       unsigned& hi, unsigned& lo) {
    unsigned h;
    asm("cvt.rn.bf16x2.f32 %0, %1, %2;" : "=r"(h) : "f"(x1), "f"(x0));
    float r0 = x0 - __uint_as_float(h << 16);
    float r1 = x1 - __uint_as_float(h & 0xffff0000u);
    unsigned l;
    asm("cvt.rn.bf16x2.f32 %0, %1, %2;" : "=r"(l) : "f"(r1), "f"(r0));
    hi = h; lo = l;
}

__device__ __forceinline__ void mma16(float* c, const unsigned* a, const unsigned* b) {
    asm volatile(
        "mma.sync.aligned.m16n8k16.row.col.f32.bf16.bf16.f32 "
        "{%0,%1,%2,%3}, {%4,%5,%6,%7}, {%8,%9}, {%0,%1,%2,%3};"
        : "+f"(c[0]), "+f"(c[1]), "+f"(c[2]), "+f"(c[3])
        : "r"(a[0]), "r"(a[1]), "r"(a[2]), "r"(a[3]), "r"(b[0]), "r"(b[1]));
}

// Issue cp.async for one 128x32 A tile into buffer at base address abuf.
__device__ __forceinline__ void issue_A(
    unsigned abuf, const float* __restrict__ A, int lda,
    int r0, int k0, int M, int tid)
{
    #pragma unroll
    for (int r = 0; r < 4; r++) {
        int i   = tid + 256 * r;       // 0..1023
        int row = i >> 3;
        int q   = i & 7;
        int gr  = r0 + row;
        int grc = min(gr, M - 1);
        cpa16(abuf + (unsigned)(row * AS + q * 4) * 4u,
              A + (size_t)grc * lda + k0 + q * 4, gr < M);
    }
    asm volatile("cp.async.commit_group;");
}

__device__ __forceinline__ void ldg_B(
    float4 br[2], const float* __restrict__ B, int ldb, int k0, int n0, int tid)
{
    #pragma unroll
    for (int r = 0; r < 2; r++) {
        int i   = tid + 256 * r;       // 0..511
        int row = i >> 4;
        int q   = i & 15;
        br[r] = *(const float4*)(B + (size_t)(k0 + row) * ldb + n0 + q * 4);
    }
}

__device__ __forceinline__ void sts_B(float* sB, const float4 br[2], int tid)
{
    #pragma unroll
    for (int r = 0; r < 2; r++) {
        int i   = tid + 256 * r;
        int row = i >> 4;
        int q   = i & 15;
        float* p = &sB[row * BSS + q * 4];
        *(float2*)(p)     = make_float2(br[r].x, br[r].y);
        *(float2*)(p + 2) = make_float2(br[r].z, br[r].w);
    }
}

// One 32-K tile of 3xBF16 math.
__device__ __forceinline__ void compute_tile(
    const float* __restrict__ sA, const float* __restrict__ sB,
    float acc[2][4][4], int lane, int wm, int wn)
{
    #pragma unroll
    for (int ks = 0; ks < 32; ks += 16) {
        unsigned ah[2][4], al[2][4];
        #pragma unroll
        for (int i = 0; i < 2; i++) {
            int rr = wm * 32 + i * 16 + (lane >> 2);
            int cc = ks + 2 * (lane & 3);
            const float* pa = sA + rr * AS + cc;
            float2 v0 = *(const float2*)(pa);               // a0: (r, k..k+1)
            float2 v1 = *(const float2*)(pa + 8 * AS);      // a1: (r+8)
            float2 v2 = *(const float2*)(pa + 8);           // a2: (r, k+8..9)
            float2 v3 = *(const float2*)(pa + 8 * AS + 8);  // a3
            split2(v0.x, v0.y, ah[i][0], al[i][0]);
            split2(v1.x, v1.y, ah[i][1], al[i][1]);
            split2(v2.x, v2.y, ah[i][2], al[i][2]);
            split2(v3.x, v3.y, ah[i][3], al[i][3]);
        }
        unsigned bh[4][2], bl[4][2];
        #pragma unroll
        for (int j = 0; j < 4; j++) {
            int cc = wn * 32 + j * 8 + (lane >> 2);
            int kb = ks + 2 * (lane & 3);
            const float* pb = sB + kb * BSS + cc;
            split2(pb[0],       pb[BSS],     bh[j][0], bl[j][0]);  // k, k+1
            split2(pb[8 * BSS], pb[9 * BSS], bh[j][1], bl[j][1]);  // k+8, k+9
        }
        #pragma unroll
        for (int i = 0; i < 2; i++)
            #pragma unroll
            for (int j = 0; j < 4; j++) {
                mma16(acc[i][j], ah[i], bh[j]);   // hi*hi
                mma16(acc[i][j], ah[i], bl[j]);   // hi*lo
                mma16(acc[i][j], al[i], bh[j]);   // lo*hi
            }
    }
}

// acc += A[r0:r0+128, 0:K] @ B[0:K, n0:n0+64], double-buffered.
__device__ __forceinline__ void gemm_db(
    const float* __restrict__ A, int lda,
    const float* __restrict__ B, int ldb,
    int K, int r0, int n0, int M,
    float* sA0, float* sA1, float* sB,
    float acc[2][4][4], int tid)
{
    int lane = tid & 31;
    int wm   = (tid >> 5) & 3;
    int wn   = tid >> 7;
    int T    = K / 32;
    unsigned ab[2] = { s2u(sA0), s2u(sA1) };
    float*   ap[2] = { sA0, sA1 };

    float4 br[2];
    issue_A(ab[0], A, lda, r0, 0, M, tid);
    ldg_B(br, B, ldb, 0, n0, tid);
    sts_B(sB, br, tid);
    asm volatile("cp.async.wait_group 0;");
    __syncthreads();

    for (int t = 0; t < T; t++) {
        if (t + 1 < T) {
            issue_A(ab[(t + 1) & 1], A, lda, r0, 32 * (t + 1), M, tid);
            ldg_B(br, B, ldb, 32 * (t + 1), n0, tid);
        }
        compute_tile(ap[t & 1], sB, acc, lane, wm, wn);
        __syncthreads();
        if (t + 1 < T) {
            sts_B(sB, br, tid);
            asm volatile("cp.async.wait_group 0;");
        }
        __syncthreads();
    }
}

__device__ __forceinline__ void store_hh2(int row, int col, float2 o) {
    __half2 p = __floats2half2_rn(o.x, o.y);
    *(__half2*)(d_hh + (size_t)row * HD + col) = p;
}

// ---------------------------------------------------------------------------
// h = x @ Win + b_in
__global__ void __launch_bounds__(256) k_gemm_in(
    const float* __restrict__ x, const float* __restrict__ Win,
    const float* __restrict__ b_in, int M)
{
    __shared__ __align__(16) float sA[2][ATILE];
    __shared__ __align__(16) float sB[BTILE];
    int tid = threadIdx.x;
    int r0  = blockIdx.x * 128;
    float acc[2][4][4] = {};

    gemm_db(x, 512, Win, HD, 512, r0, 0, M, sA[0], sA[1], sB, acc, tid);

    int lane = tid & 31, wm = (tid >> 5) & 3, wn = tid >> 7;
    #pragma unroll
    for (int i = 0; i < 2; i++) {
        int row = r0 + wm * 32 + i * 16 + (lane >> 2);
        #pragma unroll
        for (int j = 0; j < 4; j++) {
            int col = wn * 32 + j * 8 + (lane & 3) * 2;
            float2 bb = *(const float2*)(b_in + col);
            if (row < M) {
                float2 o = make_float2(acc[i][j][0] + bb.x, acc[i][j][1] + bb.y);
                *(float2*)(d_h + (size_t)row * HD + col) = o;
                store_hh2(row, col, o);
            }
            if (row + 8 < M) {
                float2 o = make_float2(acc[i][j][2] + bb.x, acc[i][j][3] + bb.y);
                *(float2*)(d_h + (size_t)(row + 8) * HD + col) = o;
                store_hh2(row + 8, col, o);
            }
        }
    }
}

// h += relu( agg @ Wl + bl + h @ Wr )  — in place.
__global__ void __launch_bounds__(256) k_layer(
    const float* __restrict__ Wl, const float* __restrict__ bl,
    const float* __restrict__ Wr, int M)
{
    __shared__ __align__(16) float sA[2][ATILE];
    __shared__ __align__(16) float sB[BTILE];
    int tid = threadIdx.x;
    int r0  = blockIdx.x * 128;
    float acc[2][4][4] = {};

    gemm_db(d_agg, HD, Wl, HD, HD, r0, 0, M, sA[0], sA[1], sB, acc, tid);
    __syncthreads();
    gemm_db(d_h,   HD, Wr, HD, HD, r0, 0, M, sA[0], sA[1], sB, acc, tid);

    int lane = tid & 31, wm = (tid >> 5) & 3, wn = tid >> 7;
    #pragma unroll
    for (int i = 0; i < 2; i++) {
        int row = r0 + wm * 32 + i * 16 + (lane >> 2);
        #pragma unroll
        for (int j = 0; j < 4; j++) {
            int col = wn * 32 + j * 8 + (lane & 3) * 2;
            float2 bb = *(const float2*)(bl + col);
            if (row < M) {
                float2 h2 = *(const float2*)(d_h + (size_t)row * HD + col);
                float2 o;
                o.x = h2.x + fmaxf(acc[i][j][0] + bb.x, 0.f);
                o.y = h2.y + fmaxf(acc[i][j][1] + bb.y, 0.f);
                *(float2*)(d_h + (size_t)row * HD + col) = o;
                store_hh2(row, col, o);
            }
            if (row + 8 < M) {
                float2 h2 = *(const float2*)(d_h + (size_t)(row + 8) * HD + col);
                float2 o;
                o.x = h2.x + fmaxf(acc[i][j][2] + bb.x, 0.f);
                o.y = h2.y + fmaxf(acc[i][j][3] + bb.y, 0.f);
                *(float2*)(d_h + (size_t)(row + 8) * HD + col) = o;
                store_hh2(row + 8, col, o);
            }
        }
    }
}

// out = h @ Wout + b_out   (N=256 tiled by blockIdx.y).
__global__ void __launch_bounds__(256) k_gemm_out(
    const float* __restrict__ Wout, const float* __restrict__ b_out,
    float* __restrict__ out, int M)
{
    __shared__ __align__(16) float sA[2][ATILE];
    __shared__ __align__(16) float sB[BTILE];
    int tid = threadIdx.x;
    int r0  = blockIdx.x * 128;
    int n0  = blockIdx.y * 64;
    float acc[2][4][4] = {};

    gemm_db(d_h, HD, Wout, 256, HD, r0, n0, M, sA[0], sA[1], sB, acc, tid);

    int lane = tid & 31, wm = (tid >> 5) & 3, wn = tid >> 7;
    #pragma unroll
    for (int i = 0; i < 2; i++) {
        int row = r0 + wm * 32 + i * 16 + (lane >> 2);
        #pragma unroll
        for (int j = 0; j < 4; j++) {
            int col = n0 + wn * 32 + j * 8 + (lane & 3) * 2;
            float2 bb = *(const float2*)(b_out + col);
            if (row < M) {
                float2 o = make_float2(acc[i][j][0] + bb.x, acc[i][j][1] + bb.y);
                *(float2*)(out + (size_t)row * 256 + col) = o;
            }
            if (row + 8 < M) {
                float2 o = make_float2(acc[i][j][2] + bb.x, acc[i][j][3] + bb.y);
                *(float2*)(out + (size_t)(row + 8) * 256 + col) = o;
            }
        }
    }
}

// ---------------------------------------------------------------------------
extern "C" void kernel_launch(void* const* d_in, const int* in_sizes, int n_in,
                              void* d_out, int out_size)
{
    const float* x     = (const float*)d_in[0];
    const int*   ei32  = (const int*)d_in[1];
    const float* Win   = (const float*)d_in[2];
    const float* b_in  = (const float*)d_in[3];
    const float* Wl    = (const float*)d_in[4];
    const float* bl    = (const float*)d_in[5];
    const float* Wr    = (const float*)d_in[6];
    const float* Wout  = (const float*)d_in[7];
    const float* b_out = (const float*)d_in[8];
    float*       out   = (float*)d_out;

    int N  = in_sizes[0] / 512;   // 100000
    int E  = in_sizes[1] / 2;     // 3200000
    int nb = (N + 255) / 256;     // 391

    // CSR build, ordered so launch #4 (ncu capture slot) is k_gemm_in.
    k_prep<<<nb, 256>>>(ei32, N);                         // 1
    k_edges<<<(E + 255) / 256, 256>>>(ei32, E);           // 2
    k_bsum<<<nb, 256>>>(N);                               // 3
    k_gemm_in<<<(N + 127) / 128, 256>>>(x, Win, b_in, N); // 4 <- profiled
    k_bscan<<<1, 512>>>(nb);                              // 5
    k_rows<<<nb, 256>>>(N, E);                            // 6
    k_fill<<<(E + 255) / 256, 256>>>(ei32, E);            // 7

    // 4 SAGE layers.
    for (int l = 0; l < 4; l++) {
        k_aggr<<<(N * 32 + 255) / 256, 256>>>(N);
        k_layer<<<(N + 127) / 128, 256>>>(Wl + (size_t)l * HD * HD,
                                          bl + (size_t)l * HD,
                                          Wr + (size_t)l * HD * HD, N);
    }

    // Output projection.
    dim3 g((N + 127) / 128, 4);
    k_gemm_out<<<g, 256>>>(Wout, b_out, out, N);
}

// round 13
// speedup vs baseline: 2.3365x; 1.1297x over previous
#include <cuda_runtime.h>
#include <cuda_fp16.h>

// ---------------------------------------------------------------------------
// GraphSAGE forward. fp32 master, fp16 message gather, 3xBF16 tensor GEMMs.
// GEMM engine: bf16 hi/lo planes in SMEM (split once at STS), ldmatrix frag
// loads, register-staged double buffering, 2 CTAs/SM.
//   h = x @ Win + b_in                                  [100000, 64]
//   4x: agg = scatter_mean(h[src] -> dst)   (CSR gather-reduce, fp16 reads)
//       h  += relu( agg @ Wl[i] + bl[i] + h @ Wr[i] )
//   out = h @ Wout + b_out                              [100000, 256]
// ---------------------------------------------------------------------------

#define NMAX 100000
#define EMAX 3200000
#define HD   64

__device__ __align__(16) float  d_h[(size_t)NMAX * HD];
__device__ __align__(16) __half d_hh[(size_t)NMAX * HD];   // fp16 shadow of h
__device__ __align__(16) float  d_agg[(size_t)NMAX * HD];
__device__ __align__(16) int    d_csr[EMAX];               // src sorted by dst
__device__ __align__(16) int    d_cnt[NMAX];
__device__ __align__(16) int    d_row[NMAX + 1];           // CSR row starts
__device__ __align__(16) int    d_woff[NMAX];              // fill cursors
__device__ __align__(16) float  d_inv[NMAX];
__device__ int d_bsum[512];
__device__ int d_boff[512];
__device__ int d_is64;

// ---------------------------------------------------------------------------
// Prologue: CSR build
// ---------------------------------------------------------------------------
__global__ void k_prep(const int* __restrict__ ei32, int N) {
    __shared__ int nz;
    int i = blockIdx.x * blockDim.x + threadIdx.x;
    if (i < N) d_cnt[i] = 0;
    if (blockIdx.x == 0) {
        if (threadIdx.x == 0) nz = 0;
        __syncthreads();
        int local = 0;
        for (int j = threadIdx.x; j < 2048; j += blockDim.x)
            if (ei32[2 * j + 1] != 0) local = 1;
        if (local) atomicOr(&nz, 1);
        __syncthreads();
        if (threadIdx.x == 0) d_is64 = (nz == 0) ? 1 : 0;
    }
}

__global__ void k_edges(const int* __restrict__ ei32, int E) {
    int e = blockIdx.x * blockDim.x + threadIdx.x;
    if (e >= E) return;
    int d = d_is64 ? ei32[2 * ((size_t)E + e)] : ei32[(size_t)E + e];
    d = min(max(d, 0), NMAX - 1);
    atomicAdd(&d_cnt[d], 1);
}

__global__ void k_bsum(int N) {
    __shared__ int sh[256];
    int i = blockIdx.x * 256 + threadIdx.x;
    int v = (i < N) ? d_cnt[i] : 0;
    sh[threadIdx.x] = v;
    __syncthreads();
    for (int s = 128; s > 0; s >>= 1) {
        if (threadIdx.x < s) sh[threadIdx.x] += sh[threadIdx.x + s];
        __syncthreads();
    }
    if (threadIdx.x == 0) d_bsum[blockIdx.x] = sh[0];
}

__global__ void k_bscan(int nb) {
    __shared__ int sh[512];
    int v = (threadIdx.x < nb) ? d_bsum[threadIdx.x] : 0;
    sh[threadIdx.x] = v;
    __syncthreads();
    for (int off = 1; off < 512; off <<= 1) {
        int t = (threadIdx.x >= off) ? sh[threadIdx.x - off] : 0;
        __syncthreads();
        sh[threadIdx.x] += t;
        __syncthreads();
    }
    if (threadIdx.x < nb) d_boff[threadIdx.x] = sh[threadIdx.x] - v;
}

__global__ void k_rows(int N, int E) {
    __shared__ int sh[256];
    int i = blockIdx.x * 256 + threadIdx.x;
    int v = (i < N) ? d_cnt[i] : 0;
    sh[threadIdx.x] = v;
    __syncthreads();
    for (int off = 1; off < 256; off <<= 1) {
        int t = (threadIdx.x >= off) ? sh[threadIdx.x - off] : 0;
        __syncthreads();
        sh[threadIdx.x] += t;
        __syncthreads();
    }
    int excl = sh[threadIdx.x] - v + d_boff[blockIdx.x];
    if (i < N) {
        d_row[i]  = excl;
        d_woff[i] = excl;
        d_inv[i]  = 1.0f / (float)max(v, 1);
    }
    if (i == N - 1) d_row[N] = E;
}

__global__ void k_fill(const int* __restrict__ ei32, int E) {
    int e = blockIdx.x * blockDim.x + threadIdx.x;
    if (e >= E) return;
    int s, d;
    if (d_is64) {
        s = ei32[2 * (size_t)e];
        d = ei32[2 * ((size_t)E + e)];
    } else {
        s = ei32[e];
        d = ei32[(size_t)E + e];
    }
    s = min(max(s, 0), NMAX - 1);
    d = min(max(d, 0), NMAX - 1);
    int pos = atomicAdd(&d_woff[d], 1);
    d_csr[pos] = s;
}

// ---------------------------------------------------------------------------
// Aggregation: one warp per node, fp16 gather, fp32 accumulate, unroll 8.
// ---------------------------------------------------------------------------
__global__ void __launch_bounds__(256) k_aggr(int N) {
    int w    = (blockIdx.x * blockDim.x + threadIdx.x) >> 5;
    int lane = threadIdx.x & 31;
    if (w >= N) return;
    int beg = d_row[w], end = d_row[w + 1];
    const __half2* hh = (const __half2*)d_hh;   // 32 half2 per row
    float2 acc = make_float2(0.f, 0.f);
    int i = beg;
    for (; i + 8 <= end; i += 8) {
        unsigned off[8];
        #pragma unroll
        for (int u = 0; u < 8; u++)
            off[u] = (unsigned)d_csr[i + u] * 32u + (unsigned)lane;
        __half2 v[8];
        #pragma unroll
        for (int u = 0; u < 8; u++)
            v[u] = hh[off[u]];
        #pragma unroll
        for (int u = 0; u < 8; u++) {
            float2 f = __half22float2(v[u]);
            acc.x += f.x;
            acc.y += f.y;
        }
    }
    for (; i < end; i++) {
        float2 f = __half22float2(hh[(unsigned)d_csr[i] * 32u + (unsigned)lane]);
        acc.x += f.x;
        acc.y += f.y;
    }
    float inv = d_inv[w];
    ((float2*)d_agg)[(unsigned)w * 32u + lane] = make_float2(acc.x * inv, acc.y * inv);
}

// ---------------------------------------------------------------------------
// 3xBF16 tensor GEMM engine, ldmatrix + bf16 hi/lo SMEM planes.
// Block 128x64, 8 warps (4 M x 2 N), warp tile 32x32 (2x4 m16n8k16).
// A planes: bf16 [128][APITCH=40]  (80B pitch: ldmatrix phase covers all banks)
// B planes: bf16 [32][BPITCH=72]   (144B pitch: same property, N=64 cols)
// Register-staged double buffer (LDG in flight during compute; single SMEM buf)
// Total SMEM = 2*10240 + 2*4608 = 29696 B -> 2 CTAs/SM.
// ---------------------------------------------------------------------------

#define APITCH 40
#define BPITCH 72
#define ASZ (128 * APITCH)   // halfs
#define BSZ (32 * BPITCH)

__device__ __forceinline__ unsigned s2u(const void* p) {
    return (unsigned)__cvta_generic_to_shared(p);
}

// two floats -> bf16x2 hi (x1 in high half, x0 low) + bf16x2 residual lo.
__device__ __forceinline__ void cvt2(float x0, float x1,
                                     unsigned& hi, unsigned& lo) {
    asm("cvt.rn.bf16x2.f32 %0, %1, %2;" : "=r"(hi) : "f"(x1), "f"(x0));
    float r0 = x0 - __uint_as_float(hi << 16);
    float r1 = x1 - __uint_as_float(hi & 0xffff0000u);
    asm("cvt.rn.bf16x2.f32 %0, %1, %2;" : "=r"(lo) : "f"(r1), "f"(r0));
}

__device__ __forceinline__ void mma16(float* c, const unsigned* a, const unsigned* b) {
    asm volatile(
        "mma.sync.aligned.m16n8k16.row.col.f32.bf16.bf16.f32 "
        "{%0,%1,%2,%3}, {%4,%5,%6,%7}, {%8,%9}, {%0,%1,%2,%3};"
        : "+f"(c[0]), "+f"(c[1]), "+f"(c[2]), "+f"(c[3])
        : "r"(a[0]), "r"(a[1]), "r"(a[2]), "r"(a[3]), "r"(b[0]), "r"(b[1]));
}

__device__ __forceinline__ void ldsm4(unsigned* r, unsigned addr) {
    asm volatile("ldmatrix.sync.aligned.m8n8.x4.shared.b16 {%0,%1,%2,%3}, [%4];"
                 : "=r"(r[0]), "=r"(r[1]), "=r"(r[2]), "=r"(r[3]) : "r"(addr));
}
__device__ __forceinline__ void ldsm4t(unsigned* r, unsigned addr) {
    asm volatile("ldmatrix.sync.aligned.m8n8.x4.trans.shared.b16 {%0,%1,%2,%3}, [%4];"
                 : "=r"(r[0]), "=r"(r[1]), "=r"(r[2]), "=r"(r[3]) : "r"(addr));
}

// --- staging: LDG fp32 -> regs; cvt+STS bf16 planes ---
__device__ __forceinline__ void ldgA(float4 v[4], const float* __restrict__ A,
                                     int lda, int r0, int k0, int M, int tid) {
    #pragma unroll
    for (int r = 0; r < 4; r++) {
        int i = tid + 256 * r, row = i >> 3, q = i & 7, gr = r0 + row;
        v[r] = (gr < M) ? *(const float4*)(A + (size_t)gr * lda + k0 + q * 4)
                        : make_float4(0.f, 0.f, 0.f, 0.f);
    }
}
__device__ __forceinline__ void stsA(const float4 v[4], __half* hi, __half* lo, int tid) {
    #pragma unroll
    for (int r = 0; r < 4; r++) {
        int i = tid + 256 * r, row = i >> 3, q = i & 7;
        int off = row * APITCH + q * 4;
        unsigned h0, l0, h1, l1;
        cvt2(v[r].x, v[r].y, h0, l0);
        cvt2(v[r].z, v[r].w, h1, l1);
        *(uint2*)(hi + off) = make_uint2(h0, h1);
        *(uint2*)(lo + off) = make_uint2(l0, l1);
    }
}
__device__ __forceinline__ void ldgB(float4 v[2], const float* __restrict__ B,
                                     int ldb, int k0, int n0, int tid) {
    #pragma unroll
    for (int r = 0; r < 2; r++) {
        int i = tid + 256 * r, row = i >> 4, q = i & 15;
        v[r] = *(const float4*)(B + (size_t)(k0 + row) * ldb + n0 + q * 4);
    }
}
__device__ __forceinline__ void stsB(const float4 v[2], __half* hi, __half* lo, int tid) {
    #pragma unroll
    for (int r = 0; r < 2; r++) {
        int i = tid + 256 * r, row = i >> 4, q = i & 15;
        int off = row * BPITCH + q * 4;
        unsigned h0, l0, h1, l1;
        cvt2(v[r].x, v[r].y, h0, l0);
        cvt2(v[r].z, v[r].w, h1, l1);
        *(uint2*)(hi + off) = make_uint2(h0, h1);
        *(uint2*)(lo + off) = make_uint2(l0, l1);
    }
}

// One 32-K tile: ldmatrix frags + 48 MMAs (3-term hi/lo).
__device__ __forceinline__ void compute_tile(
    unsigned aHi, unsigned aLo, unsigned bHi, unsigned bLo,
    float acc[2][4][4], int lane, int wm, int wn)
{
    // A: lanes 0-7 tile(m0-7,klo), 8-15 tile(m8-15,klo), 16-23 (m0-7,khi), 24-31 (m8-15,khi)
    unsigned albase = (unsigned)((lane & 15) * APITCH + (lane >> 4) * 8) * 2u;
    // B: q=lane>>3: 0:(klo,j0) 1:(khi,j0) 2:(klo,j1) 3:(khi,j1); rr = k row within tile
    unsigned q = (unsigned)lane >> 3, rr = (unsigned)lane & 7;
    unsigned blbase = (((q & 1) * 8 + rr) * BPITCH + (q >> 1) * 8) * 2u;
    unsigned amw = (unsigned)(wm * 32) * APITCH * 2u;
    unsigned bnw = (unsigned)(wn * 32) * 2u;

    #pragma unroll
    for (int ks = 0; ks < 32; ks += 16) {
        unsigned ah[2][4], al[2][4];
        #pragma unroll
        for (int i = 0; i < 2; i++) {
            unsigned off = amw + (unsigned)(i * 16) * APITCH * 2u + (unsigned)ks * 2u + albase;
            ldsm4(ah[i], aHi + off);
            ldsm4(al[i], aLo + off);
        }
        unsigned bh[4][2], bl[4][2];
        #pragma unroll
        for (int p = 0; p < 2; p++) {
            unsigned off = (unsigned)ks * BPITCH * 2u + bnw + (unsigned)(p * 16) * 2u + blbase;
            unsigned t[4];
            ldsm4t(t, bHi + off);
            bh[p * 2][0] = t[0]; bh[p * 2][1] = t[1];
            bh[p * 2 + 1][0] = t[2]; bh[p * 2 + 1][1] = t[3];
            ldsm4t(t, bLo + off);
            bl[p * 2][0] = t[0]; bl[p * 2][1] = t[1];
            bl[p * 2 + 1][0] = t[2]; bl[p * 2 + 1][1] = t[3];
        }
        #pragma unroll
        for (int i = 0; i < 2; i++)
            #pragma unroll
            for (int j = 0; j < 4; j++) {
                mma16(acc[i][j], ah[i], bh[j]);   // hi*hi
                mma16(acc[i][j], ah[i], bl[j]);   // hi*lo
                mma16(acc[i][j], al[i], bh[j]);   // lo*hi
            }
    }
}

// acc += A[r0:r0+128, 0:K] @ B[0:K, n0:n0+64], register-staged double buffer.
__device__ __forceinline__ void gemm_rdb(
    const float* __restrict__ A, int lda,
    const float* __restrict__ B, int ldb,
    int K, int r0, int n0, int M,
    __half* sAhi, __half* sAlo, __half* sBhi, __half* sBlo,
    float acc[2][4][4], int tid)
{
    int lane = tid & 31;
    int wm   = (tid >> 5) & 3;
    int wn   = tid >> 7;
    int T    = K / 32;
    unsigned aH = s2u(sAhi), aL = s2u(sAlo), bH = s2u(sBhi), bL = s2u(sBlo);

    float4 av[4], bv[2];
    ldgA(av, A, lda, r0, 0, M, tid);
    ldgB(bv, B, ldb, 0, n0, tid);
    stsA(av, sAhi, sAlo, tid);
    stsB(bv, sBhi, sBlo, tid);
    __syncthreads();

    for (int t = 0; t < T; t++) {
        if (t + 1 < T) {
            ldgA(av, A, lda, r0, 32 * (t + 1), M, tid);
            ldgB(bv, B, ldb, 32 * (t + 1), n0, tid);
        }
        compute_tile(aH, aL, bH, bL, acc, lane, wm, wn);
        __syncthreads();
        if (t + 1 < T) {
            stsA(av, sAhi, sAlo, tid);
            stsB(bv, sBhi, sBlo, tid);
            __syncthreads();
        }
    }
}

__device__ __forceinline__ void store_hh2(int row, int col, float2 o) {
    __half2 p = __floats2half2_rn(o.x, o.y);
    *(__half2*)(d_hh + (size_t)row * HD + col) = p;
}

// ---------------------------------------------------------------------------
// h = x @ Win + b_in
__global__ void __launch_bounds__(256, 2) k_gemm_in(
    const float* __restrict__ x, const float* __restrict__ Win,
    const float* __restrict__ b_in, int M)
{
    __shared__ __align__(16) __half sAhi[ASZ], sAlo[ASZ], sBhi[BSZ], sBlo[BSZ];
    int tid = threadIdx.x;
    int r0  = blockIdx.x * 128;
    float acc[2][4][4] = {};

    gemm_rdb(x, 512, Win, HD, 512, r0, 0, M, sAhi, sAlo, sBhi, sBlo, acc, tid);

    int lane = tid & 31, wm = (tid >> 5) & 3, wn = tid >> 7;
    #pragma unroll
    for (int i = 0; i < 2; i++) {
        int row = r0 + wm * 32 + i * 16 + (lane >> 2);
        #pragma unroll
        for (int j = 0; j < 4; j++) {
            int col = wn * 32 + j * 8 + (lane & 3) * 2;
            float2 bb = *(const float2*)(b_in + col);
            if (row < M) {
                float2 o = make_float2(acc[i][j][0] + bb.x, acc[i][j][1] + bb.y);
                *(float2*)(d_h + (size_t)row * HD + col) = o;
                store_hh2(row, col, o);
            }
            if (row + 8 < M) {
                float2 o = make_float2(acc[i][j][2] + bb.x, acc[i][j][3] + bb.y);
                *(float2*)(d_h + (size_t)(row + 8) * HD + col) = o;
                store_hh2(row + 8, col, o);
            }
        }
    }
}

// h += relu( agg @ Wl + bl + h @ Wr )  — in place.
__global__ void __launch_bounds__(256, 2) k_layer(
    const float* __restrict__ Wl, const float* __restrict__ bl,
    const float* __restrict__ Wr, int M)
{
    __shared__ __align__(16) __half sAhi[ASZ], sAlo[ASZ], sBhi[BSZ], sBlo[BSZ];
    int tid = threadIdx.x;
    int r0  = blockIdx.x * 128;
    float acc[2][4][4] = {};

    gemm_rdb(d_agg, HD, Wl, HD, HD, r0, 0, M, sAhi, sAlo, sBhi, sBlo, acc, tid);
    gemm_rdb(d_h,   HD, Wr, HD, HD, r0, 0, M, sAhi, sAlo, sBhi, sBlo, acc, tid);

    int lane = tid & 31, wm = (tid >> 5) & 3, wn = tid >> 7;
    #pragma unroll
    for (int i = 0; i < 2; i++) {
        int row = r0 + wm * 32 + i * 16 + (lane >> 2);
        #pragma unroll
        for (int j = 0; j < 4; j++) {
            int col = wn * 32 + j * 8 + (lane & 3) * 2;
            float2 bb = *(const float2*)(bl + col);
            if (row < M) {
                float2 h2 = *(const float2*)(d_h + (size_t)row * HD + col);
                float2 o;
                o.x = h2.x + fmaxf(acc[i][j][0] + bb.x, 0.f);
                o.y = h2.y + fmaxf(acc[i][j][1] + bb.y, 0.f);
                *(float2*)(d_h + (size_t)row * HD + col) = o;
                store_hh2(row, col, o);
            }
            if (row + 8 < M) {
                float2 h2 = *(const float2*)(d_h + (size_t)(row + 8) * HD + col);
                float2 o;
                o.x = h2.x + fmaxf(acc[i][j][2] + bb.x, 0.f);
                o.y = h2.y + fmaxf(acc[i][j][3] + bb.y, 0.f);
                *(float2*)(d_h + (size_t)(row + 8) * HD + col) = o;
                store_hh2(row + 8, col, o);
            }
        }
    }
}

// out = h @ Wout + b_out   (N=256 tiled by blockIdx.y).
__global__ void __launch_bounds__(256, 2) k_gemm_out(
    const float* __restrict__ Wout, const float* __restrict__ b_out,
    float* __restrict__ out, int M)
{
    __shared__ __align__(16) __half sAhi[ASZ], sAlo[ASZ], sBhi[BSZ], sBlo[BSZ];
    int tid = threadIdx.x;
    int r0  = blockIdx.x * 128;
    int n0  = blockIdx.y * 64;
    float acc[2][4][4] = {};

    gemm_rdb(d_h, HD, Wout, 256, HD, r0, n0, M, sAhi, sAlo, sBhi, sBlo, acc, tid);

    int lane = tid & 31, wm = (tid >> 5) & 3, wn = tid >> 7;
    #pragma unroll
    for (int i = 0; i < 2; i++) {
        int row = r0 + wm * 32 + i * 16 + (lane >> 2);
        #pragma unroll
        for (int j = 0; j < 4; j++) {
            int col = n0 + wn * 32 + j * 8 + (lane & 3) * 2;
            float2 bb = *(const float2*)(b_out + col);
            if (row < M) {
                float2 o = make_float2(acc[i][j][0] + bb.x, acc[i][j][1] + bb.y);
                *(float2*)(out + (size_t)row * 256 + col) = o;
            }
            if (row + 8 < M) {
                float2 o = make_float2(acc[i][j][2] + bb.x, acc[i][j][3] + bb.y);
                *(float2*)(out + (size_t)(row + 8) * 256 + col) = o;
            }
        }
    }
}

// ---------------------------------------------------------------------------
extern "C" void kernel_launch(void* const* d_in, const int* in_sizes, int n_in,
                              void* d_out, int out_size)
{
    const float* x     = (const float*)d_in[0];
    const int*   ei32  = (const int*)d_in[1];
    const float* Win   = (const float*)d_in[2];
    const float* b_in  = (const float*)d_in[3];
    const float* Wl    = (const float*)d_in[4];
    const float* bl    = (const float*)d_in[5];
    const float* Wr    = (const float*)d_in[6];
    const float* Wout  = (const float*)d_in[7];
    const float* b_out = (const float*)d_in[8];
    float*       out   = (float*)d_out;

    int N  = in_sizes[0] / 512;   // 100000
    int E  = in_sizes[1] / 2;     // 3200000
    int nb = (N + 255) / 256;     // 391

    // CSR build, ordered so launch #4 (ncu capture slot) is k_gemm_in.
    k_prep<<<nb, 256>>>(ei32, N);                         // 1
    k_edges<<<(E + 255) / 256, 256>>>(ei32, E);           // 2
    k_bsum<<<nb, 256>>>(N);                               // 3
    k_gemm_in<<<(N + 127) / 128, 256>>>(x, Win, b_in, N); // 4 <- profiled
    k_bscan<<<1, 512>>>(nb);                              // 5
    k_rows<<<nb, 256>>>(N, E);                            // 6
    k_fill<<<(E + 255) / 256, 256>>>(ei32, E);            // 7

    // 4 SAGE layers.
    for (int l = 0; l < 4; l++) {
        k_aggr<<<(N * 32 + 255) / 256, 256>>>(N);
        k_layer<<<(N + 127) / 128, 256>>>(Wl + (size_t)l * HD * HD,
                                          bl + (size_t)l * HD,
                                          Wr + (size_t)l * HD * HD, N);
    }

    // Output projection.
    dim3 g((N + 127) / 128, 4);
    k_gemm_out<<<g, 256>>>(Wout, b_out, out, N);
}